// round 5
// baseline (speedup 1.0000x reference)
#include <cuda_runtime.h>
#include <cuda_bf16.h>
#include <cstdint>

#define DIMV 768
#define TTOK 16384
#define HID  3072
#define NQKV 2304

// ---------------- device scratch (allocation-free rule: __device__ globals) -------------
__device__ __align__(256) __nv_bfloat16 g_act_hi[(size_t)TTOK * DIMV];
__device__ __align__(256) __nv_bfloat16 g_act_lo[(size_t)TTOK * DIMV];
__device__ __align__(256) float         g_qkv[(size_t)TTOK * NQKV];
__device__ __align__(256) float         g_y[(size_t)TTOK * DIMV];
__device__ __align__(256) __nv_bfloat16 g_h_hi[(size_t)TTOK * HID];
__device__ __align__(256) __nv_bfloat16 g_h_lo[(size_t)TTOK * HID];
__device__ __align__(256) __nv_bfloat16 g_wqkv_hi[(size_t)NQKV * DIMV];
__device__ __align__(256) __nv_bfloat16 g_wqkv_lo[(size_t)NQKV * DIMV];
__device__ __align__(256) __nv_bfloat16 g_w1_hi[(size_t)HID * DIMV];
__device__ __align__(256) __nv_bfloat16 g_w1_lo[(size_t)HID * DIMV];
__device__ __align__(256) __nv_bfloat16 g_w2_hi[(size_t)DIMV * HID];
__device__ __align__(256) __nv_bfloat16 g_w2_lo[(size_t)DIMV * HID];
__device__ __align__(256) float         g_qkvb[NQKV];

extern __shared__ char dyn_smem[];

// ---------------- PTX helpers (compute_103-baseline only) -------------------
__device__ __forceinline__ uint32_t smem_u32(const void* p) {
    uint32_t a;
    asm("{ .reg .u64 t; cvta.to.shared.u64 t, %1; cvt.u32.u64 %0, t; }" : "=r"(a) : "l"(p));
    return a;
}
__device__ __forceinline__ void cp16(uint32_t smaddr, const void* g) {
    asm volatile("cp.async.cg.shared.global [%0], [%1], 16;" :: "r"(smaddr), "l"(g) : "memory");
}
#define CP_COMMIT() asm volatile("cp.async.commit_group;" ::: "memory")
#define CP_WAIT(n)  asm volatile("cp.async.wait_group %0;" :: "n"(n) : "memory")

__device__ __forceinline__ void ldsm_x4(uint32_t* r, uint32_t addr) {
    asm volatile("ldmatrix.sync.aligned.m8n8.x4.shared.b16 {%0,%1,%2,%3}, [%4];"
                 : "=r"(r[0]), "=r"(r[1]), "=r"(r[2]), "=r"(r[3]) : "r"(addr));
}
__device__ __forceinline__ void ldsm_x2(uint32_t* r, uint32_t addr) {
    asm volatile("ldmatrix.sync.aligned.m8n8.x2.shared.b16 {%0,%1}, [%2];"
                 : "=r"(r[0]), "=r"(r[1]) : "r"(addr));
}
__device__ __forceinline__ void mma16816(float* c, const uint32_t* a, const uint32_t* b) {
    asm volatile("mma.sync.aligned.m16n8k16.row.col.f32.bf16.bf16.f32 "
                 "{%0,%1,%2,%3}, {%4,%5,%6,%7}, {%8,%9}, {%0,%1,%2,%3};"
                 : "+f"(c[0]), "+f"(c[1]), "+f"(c[2]), "+f"(c[3])
                 : "r"(a[0]), "r"(a[1]), "r"(a[2]), "r"(a[3]), "r"(b[0]), "r"(b[1]));
}

// ---------------- small helpers ----------------
__device__ __forceinline__ void split_store(float v, __nv_bfloat16* hi, __nv_bfloat16* lo, size_t idx) {
    __nv_bfloat16 h = __float2bfloat16(v);
    hi[idx] = h;
    lo[idx] = __float2bfloat16(v - __bfloat162float(h));
}
__device__ __forceinline__ float warp_sum(float v) {
    #pragma unroll
    for (int o = 16; o > 0; o >>= 1) v += __shfl_xor_sync(0xffffffffu, v, o);
    return v;
}

// ---------------- prep kernels ----------------
__global__ void prep_qkv(const float* __restrict__ wq, const float* __restrict__ wk,
                         const float* __restrict__ wv, const float* __restrict__ bq,
                         const float* __restrict__ bk, const float* __restrict__ bv) {
    const int n = DIMV * DIMV;
    for (int i = blockIdx.x * blockDim.x + threadIdx.x; i < 3 * n + NQKV; i += gridDim.x * blockDim.x) {
        if (i < 3 * n) {
            int s = i / n, j = i - s * n;
            const float* w = (s == 0) ? wq : (s == 1) ? wk : wv;
            float v = w[j];
            __nv_bfloat16 h = __float2bfloat16(v);
            g_wqkv_hi[(size_t)s * n + j] = h;
            g_wqkv_lo[(size_t)s * n + j] = __float2bfloat16(v - __bfloat162float(h));
        } else {
            int j = i - 3 * n;
            g_qkvb[j] = (j < 768) ? bq[j] : (j < 1536) ? bk[j - 768] : bv[j - 1536];
        }
    }
}
__global__ void prep_mlp(const float* __restrict__ d1, const float* __restrict__ d2) {
    const int n = HID * DIMV;
    for (int i = blockIdx.x * blockDim.x + threadIdx.x; i < 2 * n; i += gridDim.x * blockDim.x) {
        if (i < n) {
            float v = d1[i];
            __nv_bfloat16 h = __float2bfloat16(v);
            g_w1_hi[i] = h;
            g_w1_lo[i] = __float2bfloat16(v - __bfloat162float(h));
        } else {
            int j = i - n;
            float v = d2[j];
            __nv_bfloat16 h = __float2bfloat16(v);
            g_w2_hi[j] = h;
            g_w2_lo[j] = __float2bfloat16(v - __bfloat162float(h));
        }
    }
}

// ---------------- LN1 ----------------
__global__ void ln1_kernel(const float* __restrict__ x, const float* __restrict__ g1,
                           const float* __restrict__ b1) {
    int wid = threadIdx.x >> 5, lid = threadIdx.x & 31;
    int tok = blockIdx.x * 8 + wid;
    const float* xr = x + (size_t)tok * DIMV;
    float xv[24];
    #pragma unroll
    for (int j = 0; j < 24; ++j) xv[j] = xr[lid + 32 * j];
    float s = 0.f;
    #pragma unroll
    for (int j = 0; j < 24; ++j) s += xv[j];
    float mean = warp_sum(s) * (1.0f / DIMV);
    float s2 = 0.f;
    #pragma unroll
    for (int j = 0; j < 24; ++j) { float d = xv[j] - mean; s2 += d * d; }
    float var = warp_sum(s2) * (1.0f / (DIMV - 1));
    float inv = g1[0] / (sqrtf(var) + 1e-6f);
    float bb = b1[0];
    size_t base = (size_t)tok * DIMV;
    #pragma unroll
    for (int j = 0; j < 24; ++j) {
        float n = (xv[j] - mean) * inv + bb;
        split_store(n, g_act_hi, g_act_lo, base + lid + 32 * j);
    }
}

// ---------------- attention + residual + LN2 (+split) ----------------
__global__ void attn_ln2_kernel(const float* __restrict__ x, const float* __restrict__ g2,
                                const float* __restrict__ b2) {
    float* ks = (float*)dyn_smem;
    float* vs = ks + 8 * DIMV;
    int tid = threadIdx.x;
    int wid = tid >> 5, lid = tid & 31;
    int t0 = blockIdx.x * 8;
    for (int i = tid; i < 8 * DIMV; i += 256) {
        int r = i / DIMV, c = i - r * DIMV;
        const float* row = g_qkv + (size_t)(t0 + r) * NQKV;
        ks[i] = row[768 + c];
        vs[i] = row[1536 + c];
    }
    __syncthreads();
    int h = wid;
    const float* qr = g_qkv + (size_t)(t0 + h) * NQKV;
    float qv[24];
    #pragma unroll
    for (int j = 0; j < 24; ++j) qv[j] = qr[lid + 32 * j];
    float p[8];
    #pragma unroll
    for (int kk = 0; kk < 8; ++kk) {
        float acc = 0.f;
        const float* kr = ks + kk * DIMV;
        #pragma unroll
        for (int j = 0; j < 24; ++j) acc += qv[j] * kr[lid + 32 * j];
        p[kk] = acc;
    }
    #pragma unroll
    for (int kk = 0; kk < 8; ++kk) p[kk] = warp_sum(p[kk]) * 0.03608439182435161f;
    float m = p[0];
    #pragma unroll
    for (int kk = 1; kk < 8; ++kk) m = fmaxf(m, p[kk]);
    float se = 0.f;
    #pragma unroll
    for (int kk = 0; kk < 8; ++kk) { p[kk] = __expf(p[kk] - m); se += p[kk]; }
    float rinv = 1.0f / se;
    #pragma unroll
    for (int kk = 0; kk < 8; ++kk) p[kk] *= rinv;
    const float* xr = x + (size_t)(t0 + h) * DIMV;
    float yv[24];
    #pragma unroll
    for (int j = 0; j < 24; ++j) {
        int d = lid + 32 * j;
        float a = 0.f;
        #pragma unroll
        for (int kk = 0; kk < 8; ++kk) a += p[kk] * vs[kk * DIMV + d];
        yv[j] = a + xr[d];
    }
    size_t base = (size_t)(t0 + h) * DIMV;
    #pragma unroll
    for (int j = 0; j < 24; ++j) g_y[base + lid + 32 * j] = yv[j];
    float s = 0.f;
    #pragma unroll
    for (int j = 0; j < 24; ++j) s += yv[j];
    float mean = warp_sum(s) * (1.0f / DIMV);
    float s2 = 0.f;
    #pragma unroll
    for (int j = 0; j < 24; ++j) { float d = yv[j] - mean; s2 += d * d; }
    float var = warp_sum(s2) * (1.0f / (DIMV - 1));
    float inv = g2[0] / (sqrtf(var) + 1e-6f);
    float bb = b2[0];
    #pragma unroll
    for (int j = 0; j < 24; ++j) {
        float n = (yv[j] - mean) * inv + bb;
        split_store(n, g_act_hi, g_act_lo, base + lid + 32 * j);
    }
}

// ---------------- mma.sync GEMM: 128x192 tile, 6 warps (2x3, warp tile 64x64), -----------
// BK=32, 2-stage cp.async, 2 CTAs/SM. stage: Ahi(128x80B) Alo Bhi(192x80B) Blo = 51200 B
#define ST_A    10240
#define ST_B    15360
#define ST_SIZE 51200
#define GEMM_SMEM (2 * ST_SIZE)

// EPI 0: act @ wqkv^T + qkvb  -> g_qkv          (K=768,  N=2304)
// EPI 1: act @ w1^T + d1_b, gelu, split -> g_h  (K=768,  N=3072)
// EPI 2: h @ w2^T + d2_b + g_y -> outF          (K=3072, N=768)
template <int EPI>
__global__ void __launch_bounds__(192, 2) gemm_k(const float* __restrict__ bias, float* __restrict__ outF) {
    constexpr int Kd = (EPI == 2) ? HID : DIMV;
    constexpr int NCH = Kd / 32;
    const __nv_bfloat16* Ahi = (EPI == 2) ? g_h_hi : g_act_hi;
    const __nv_bfloat16* Alo = (EPI == 2) ? g_h_lo : g_act_lo;
    const __nv_bfloat16* Bhi = (EPI == 0) ? g_wqkv_hi : (EPI == 1) ? g_w1_hi : g_w2_hi;
    const __nv_bfloat16* Blo = (EPI == 0) ? g_wqkv_lo : (EPI == 1) ? g_w1_lo : g_w2_lo;

    const int tid = threadIdx.x;
    const int lane = tid & 31, wid = tid >> 5;
    const int wm = (wid < 3) ? 0 : 1, wn = (wid < 3) ? wid : wid - 3;  // 2 x 3 grid, tile 64x64
    const int bx = blockIdx.x, by = blockIdx.y;
    const uint32_t smb = smem_u32(dyn_smem);

    auto load_stage = [&](int c, int st) {
        uint32_t sb = smb + st * ST_SIZE;
        #pragma unroll
        for (int s = 0; s < 2; ++s) {           // Ahi, Alo: 128 rows x 64B = 512 cp16
            const __nv_bfloat16* src = s ? Alo : Ahi;
            for (int i = tid; i < 512; i += 192) {
                int r = i >> 2, q = i & 3;
                cp16(sb + s * ST_A + r * 80 + q * 16,
                     src + (size_t)(by * 128 + r) * Kd + c * 32 + q * 8);
            }
        }
        #pragma unroll
        for (int s = 0; s < 2; ++s) {           // Bhi, Blo: 192 rows x 64B = 768 cp16
            const __nv_bfloat16* src = s ? Blo : Bhi;
            for (int i = tid; i < 768; i += 192) {
                int r = i >> 2, q = i & 3;
                cp16(sb + 2 * ST_A + s * ST_B + r * 80 + q * 16,
                     src + (size_t)(bx * 192 + r) * Kd + c * 32 + q * 8);
            }
        }
        CP_COMMIT();
    };

    float acc[4][8][4];
    #pragma unroll
    for (int mi = 0; mi < 4; ++mi)
        #pragma unroll
        for (int ni = 0; ni < 8; ++ni)
            #pragma unroll
            for (int r = 0; r < 4; ++r) acc[mi][ni][r] = 0.f;

    load_stage(0, 0);

    for (int c = 0; c < NCH; ++c) {
        __syncthreads();                        // all warps done reading buf (c+1)&1 (iter c-1)
        if (c + 1 < NCH) {
            load_stage(c + 1, (c + 1) & 1);
            CP_WAIT(1);                         // group c complete, c+1 in flight
        } else {
            CP_WAIT(0);
        }
        __syncthreads();                        // stage c visible to all warps

        const uint32_t sb = smb + (c & 1) * ST_SIZE;
        #pragma unroll
        for (int ks = 0; ks < 2; ++ks) {
            uint32_t ahi[4][4], alo[4][4];
            #pragma unroll
            for (int mi = 0; mi < 4; ++mi) {
                uint32_t ad = sb + (uint32_t)(wm * 64 + mi * 16 + (lane & 15)) * 80
                            + ks * 32 + (lane >> 4) * 16;
                ldsm_x4(ahi[mi], ad);
                ldsm_x4(alo[mi], ad + ST_A);
            }
            #pragma unroll
            for (int ni = 0; ni < 8; ++ni) {
                uint32_t bhi[2], blo[2];
                uint32_t bd = sb + 2 * ST_A + (uint32_t)(wn * 64 + ni * 8 + (lane & 7)) * 80
                            + ks * 32 + ((lane >> 3) & 1) * 16;
                ldsm_x2(bhi, bd);
                ldsm_x2(blo, bd + ST_B);
                #pragma unroll
                for (int mi = 0; mi < 4; ++mi) {
                    mma16816(acc[mi][ni], ahi[mi], bhi);
                    mma16816(acc[mi][ni], ahi[mi], blo);
                    mma16816(acc[mi][ni], alo[mi], bhi);
                }
            }
        }
    }

    // ---------------- epilogue ----------------
    const int r0 = lane >> 2, c0 = 2 * (lane & 3);
    #pragma unroll
    for (int mi = 0; mi < 4; ++mi) {
        #pragma unroll
        for (int hh = 0; hh < 2; ++hh) {
            const int grow = by * 128 + wm * 64 + mi * 16 + r0 + hh * 8;
            #pragma unroll
            for (int ni = 0; ni < 8; ++ni) {
                const int gcol = bx * 192 + wn * 64 + ni * 8 + c0;
                float v0 = acc[mi][ni][2 * hh + 0];
                float v1 = acc[mi][ni][2 * hh + 1];
                if (EPI == 0) {
                    float2 o;
                    o.x = v0 + g_qkvb[gcol];
                    o.y = v1 + g_qkvb[gcol + 1];
                    *(float2*)(g_qkv + (size_t)grow * NQKV + gcol) = o;
                } else if (EPI == 1) {
                    float u0 = v0 + bias[gcol];
                    float u1 = v1 + bias[gcol + 1];
                    float gl0 = 0.5f * u0 * (1.0f + erff(u0 * 0.70710678118654752440f));
                    float gl1 = 0.5f * u1 * (1.0f + erff(u1 * 0.70710678118654752440f));
                    __nv_bfloat16 h0 = __float2bfloat16(gl0);
                    __nv_bfloat16 h1 = __float2bfloat16(gl1);
                    __nv_bfloat16 l0 = __float2bfloat16(gl0 - __bfloat162float(h0));
                    __nv_bfloat16 l1 = __float2bfloat16(gl1 - __bfloat162float(h1));
                    size_t idx = (size_t)grow * HID + gcol;
                    *(__nv_bfloat162*)(g_h_hi + idx) = __nv_bfloat162(h0, h1);
                    *(__nv_bfloat162*)(g_h_lo + idx) = __nv_bfloat162(l0, l1);
                } else {
                    size_t idx = (size_t)grow * DIMV + gcol;
                    float2 res = *(const float2*)(g_y + idx);
                    float2 o;
                    o.x = v0 + bias[gcol] + res.x;
                    o.y = v1 + bias[gcol + 1] + res.y;
                    *(float2*)(outF + idx) = o;
                }
            }
        }
    }
}

// ---------------- launch ----------------
#define ATTN_SMEM (2 * 8 * DIMV * (int)sizeof(float))

extern "C" void kernel_launch(void* const* d_in, const int* in_sizes, int n_in,
                              void* d_out, int out_size) {
    const float* x    = (const float*)d_in[0];
    const float* wq_w = (const float*)d_in[1];
    const float* wq_b = (const float*)d_in[2];
    const float* wk_w = (const float*)d_in[3];
    const float* wk_b = (const float*)d_in[4];
    const float* wv_w = (const float*)d_in[5];
    const float* wv_b = (const float*)d_in[6];
    const float* d1_w = (const float*)d_in[7];
    const float* d1_b = (const float*)d_in[8];
    const float* d2_w = (const float*)d_in[9];
    const float* d2_b = (const float*)d_in[10];
    const float* g1   = (const float*)d_in[11];
    const float* b1   = (const float*)d_in[12];
    const float* g2   = (const float*)d_in[13];
    const float* b2   = (const float*)d_in[14];
    float* out = (float*)d_out;

    cudaFuncSetAttribute(gemm_k<0>, cudaFuncAttributeMaxDynamicSharedMemorySize, GEMM_SMEM);
    cudaFuncSetAttribute(gemm_k<1>, cudaFuncAttributeMaxDynamicSharedMemorySize, GEMM_SMEM);
    cudaFuncSetAttribute(gemm_k<2>, cudaFuncAttributeMaxDynamicSharedMemorySize, GEMM_SMEM);
    cudaFuncSetAttribute(attn_ln2_kernel, cudaFuncAttributeMaxDynamicSharedMemorySize, ATTN_SMEM);

    // launch order chosen so ncu (-s 5 -c 1) profiles gemm_k<1>, the largest GEMM
    prep_qkv<<<2048, 256>>>(wq_w, wk_w, wv_w, wq_b, wk_b, wv_b);       // 0
    prep_mlp<<<4096, 256>>>(d1_w, d2_w);                               // 1
    ln1_kernel<<<TTOK / 8, 256>>>(x, g1, b1);                          // 2
    gemm_k<0><<<dim3(NQKV / 192, TTOK / 128), 192, GEMM_SMEM>>>(nullptr, nullptr);  // 3
    attn_ln2_kernel<<<TTOK / 8, 256, ATTN_SMEM>>>(x, g2, b2);          // 4
    gemm_k<1><<<dim3(HID / 192, TTOK / 128), 192, GEMM_SMEM>>>(d1_b, nullptr);      // 5 <- profiled
    gemm_k<2><<<dim3(DIMV / 192, TTOK / 128), 192, GEMM_SMEM>>>(d2_b, out);         // 6
}

// round 6
// speedup vs baseline: 1.3766x; 1.3766x over previous
#include <cuda_runtime.h>
#include <cuda_bf16.h>
#include <cuda_fp16.h>
#include <cstdint>

#define DIMV 768
#define TTOK 16384
#define HID  3072
#define NQKV 2304

// ---------------- device scratch (allocation-free rule: __device__ globals) -------------
__device__ __align__(256) __half g_act[(size_t)TTOK * DIMV];
__device__ __align__(256) float  g_qkv[(size_t)TTOK * NQKV];
__device__ __align__(256) float  g_y[(size_t)TTOK * DIMV];
__device__ __align__(256) __half g_h[(size_t)TTOK * HID];
__device__ __align__(256) __half g_wqkv_hi[(size_t)NQKV * DIMV];
__device__ __align__(256) __half g_wqkv_lo[(size_t)NQKV * DIMV];
__device__ __align__(256) __half g_w1_hi[(size_t)HID * DIMV];
__device__ __align__(256) __half g_w1_lo[(size_t)HID * DIMV];
__device__ __align__(256) __half g_w2_hi[(size_t)DIMV * HID];
__device__ __align__(256) __half g_w2_lo[(size_t)DIMV * HID];
__device__ __align__(256) float  g_qkvb[NQKV];

extern __shared__ char dyn_smem[];

// ---------------- PTX helpers ----------------
__device__ __forceinline__ uint32_t smem_u32(const void* p) {
    uint32_t a;
    asm("{ .reg .u64 t; cvta.to.shared.u64 t, %1; cvt.u32.u64 %0, t; }" : "=r"(a) : "l"(p));
    return a;
}
__device__ __forceinline__ void cp16(uint32_t smaddr, const void* g) {
    asm volatile("cp.async.cg.shared.global [%0], [%1], 16;" :: "r"(smaddr), "l"(g) : "memory");
}
#define CP_COMMIT() asm volatile("cp.async.commit_group;" ::: "memory")
#define CP_WAIT(n)  asm volatile("cp.async.wait_group %0;" :: "n"(n) : "memory")

__device__ __forceinline__ void ldsm_x4(uint32_t* r, uint32_t addr) {
    asm volatile("ldmatrix.sync.aligned.m8n8.x4.shared.b16 {%0,%1,%2,%3}, [%4];"
                 : "=r"(r[0]), "=r"(r[1]), "=r"(r[2]), "=r"(r[3]) : "r"(addr));
}
__device__ __forceinline__ void mma16816h(float* c, const uint32_t* a, const uint32_t* b) {
    asm volatile("mma.sync.aligned.m16n8k16.row.col.f32.f16.f16.f32 "
                 "{%0,%1,%2,%3}, {%4,%5,%6,%7}, {%8,%9}, {%0,%1,%2,%3};"
                 : "+f"(c[0]), "+f"(c[1]), "+f"(c[2]), "+f"(c[3])
                 : "r"(a[0]), "r"(a[1]), "r"(a[2]), "r"(a[3]), "r"(b[0]), "r"(b[1]));
}

// ---------------- small helpers ----------------
__device__ __forceinline__ float warp_sum(float v) {
    #pragma unroll
    for (int o = 16; o > 0; o >>= 1) v += __shfl_xor_sync(0xffffffffu, v, o);
    return v;
}

// ---------------- prep kernels ----------------
__global__ void prep_qkv(const float* __restrict__ wq, const float* __restrict__ wk,
                         const float* __restrict__ wv, const float* __restrict__ bq,
                         const float* __restrict__ bk, const float* __restrict__ bv) {
    const int n = DIMV * DIMV;
    for (int i = blockIdx.x * blockDim.x + threadIdx.x; i < 3 * n + NQKV; i += gridDim.x * blockDim.x) {
        if (i < 3 * n) {
            int s = i / n, j = i - s * n;
            const float* w = (s == 0) ? wq : (s == 1) ? wk : wv;
            float v = w[j];
            __half h = __float2half(v);
            g_wqkv_hi[(size_t)s * n + j] = h;
            g_wqkv_lo[(size_t)s * n + j] = __float2half(v - __half2float(h));
        } else {
            int j = i - 3 * n;
            g_qkvb[j] = (j < 768) ? bq[j] : (j < 1536) ? bk[j - 768] : bv[j - 1536];
        }
    }
}
__global__ void prep_mlp(const float* __restrict__ d1, const float* __restrict__ d2) {
    const int n = HID * DIMV;
    for (int i = blockIdx.x * blockDim.x + threadIdx.x; i < 2 * n; i += gridDim.x * blockDim.x) {
        if (i < n) {
            float v = d1[i];
            __half h = __float2half(v);
            g_w1_hi[i] = h;
            g_w1_lo[i] = __float2half(v - __half2float(h));
        } else {
            int j = i - n;
            float v = d2[j];
            __half h = __float2half(v);
            g_w2_hi[j] = h;
            g_w2_lo[j] = __float2half(v - __half2float(h));
        }
    }
}

// ---------------- LN1: x -> fp16(layernorm(x)) ; warp per token ----------------
__global__ void ln1_kernel(const float* __restrict__ x, const float* __restrict__ g1,
                           const float* __restrict__ b1) {
    int wid = threadIdx.x >> 5, lid = threadIdx.x & 31;
    int tok = blockIdx.x * 8 + wid;
    const float* xr = x + (size_t)tok * DIMV;
    float xv[24];
    #pragma unroll
    for (int j = 0; j < 24; ++j) xv[j] = xr[lid + 32 * j];
    float s = 0.f;
    #pragma unroll
    for (int j = 0; j < 24; ++j) s += xv[j];
    float mean = warp_sum(s) * (1.0f / DIMV);
    float s2 = 0.f;
    #pragma unroll
    for (int j = 0; j < 24; ++j) { float d = xv[j] - mean; s2 += d * d; }
    float var = warp_sum(s2) * (1.0f / (DIMV - 1));
    float inv = g1[0] / (sqrtf(var) + 1e-6f);
    float bb = b1[0];
    size_t base = (size_t)tok * DIMV;
    #pragma unroll
    for (int j = 0; j < 24; ++j)
        g_act[base + lid + 32 * j] = __float2half((xv[j] - mean) * inv + bb);
}

// ---------------- attention + residual + LN2 ----------------
__global__ void attn_ln2_kernel(const float* __restrict__ x, const float* __restrict__ g2,
                                const float* __restrict__ b2) {
    float* ks = (float*)dyn_smem;
    float* vs = ks + 8 * DIMV;
    int tid = threadIdx.x;
    int wid = tid >> 5, lid = tid & 31;
    int t0 = blockIdx.x * 8;
    for (int i = tid; i < 8 * DIMV; i += 256) {
        int r = i / DIMV, c = i - r * DIMV;
        const float* row = g_qkv + (size_t)(t0 + r) * NQKV;
        ks[i] = row[768 + c];
        vs[i] = row[1536 + c];
    }
    __syncthreads();
    int h = wid;
    const float* qr = g_qkv + (size_t)(t0 + h) * NQKV;
    float qv[24];
    #pragma unroll
    for (int j = 0; j < 24; ++j) qv[j] = qr[lid + 32 * j];
    float p[8];
    #pragma unroll
    for (int kk = 0; kk < 8; ++kk) {
        float acc = 0.f;
        const float* kr = ks + kk * DIMV;
        #pragma unroll
        for (int j = 0; j < 24; ++j) acc += qv[j] * kr[lid + 32 * j];
        p[kk] = acc;
    }
    #pragma unroll
    for (int kk = 0; kk < 8; ++kk) p[kk] = warp_sum(p[kk]) * 0.03608439182435161f;
    float m = p[0];
    #pragma unroll
    for (int kk = 1; kk < 8; ++kk) m = fmaxf(m, p[kk]);
    float se = 0.f;
    #pragma unroll
    for (int kk = 0; kk < 8; ++kk) { p[kk] = __expf(p[kk] - m); se += p[kk]; }
    float rinv = 1.0f / se;
    #pragma unroll
    for (int kk = 0; kk < 8; ++kk) p[kk] *= rinv;
    const float* xr = x + (size_t)(t0 + h) * DIMV;
    float yv[24];
    #pragma unroll
    for (int j = 0; j < 24; ++j) {
        int d = lid + 32 * j;
        float a = 0.f;
        #pragma unroll
        for (int kk = 0; kk < 8; ++kk) a += p[kk] * vs[kk * DIMV + d];
        yv[j] = a + xr[d];
    }
    size_t base = (size_t)(t0 + h) * DIMV;
    #pragma unroll
    for (int j = 0; j < 24; ++j) g_y[base + lid + 32 * j] = yv[j];
    float s = 0.f;
    #pragma unroll
    for (int j = 0; j < 24; ++j) s += yv[j];
    float mean = warp_sum(s) * (1.0f / DIMV);
    float s2 = 0.f;
    #pragma unroll
    for (int j = 0; j < 24; ++j) { float d = yv[j] - mean; s2 += d * d; }
    float var = warp_sum(s2) * (1.0f / (DIMV - 1));
    float inv = g2[0] / (sqrtf(var) + 1e-6f);
    float bb = b2[0];
    #pragma unroll
    for (int j = 0; j < 24; ++j)
        g_act[base + lid + 32 * j] = __float2half((yv[j] - mean) * inv + bb);
}

// ---------------- fp16 mma GEMM: 128x256 tile, 8 warps (2x4, warp 64x64) ----------------
// A single fp16, B split hi/lo -> 2 MMAs per k16.
// Stage: A(128x80B) + Bhi(256x80B) + Blo(256x80B) = 51200 B; 4 stages.
#define ST_A    10240
#define ST_B    20480
#define ST_SIZE 51200
#define N_STAGE 4
#define GEMM_SMEM (N_STAGE * ST_SIZE)

// EPI 0: act @ wqkv^T + qkvb  -> g_qkv          (K=768,  N=2304)
// EPI 1: act @ w1^T + d1_b, gelu -> g_h (fp16)  (K=768,  N=3072)
// EPI 2: h @ w2^T + d2_b + g_y -> outF          (K=3072, N=768)
template <int EPI>
__global__ void __launch_bounds__(256) gemm_k(const float* __restrict__ bias, float* __restrict__ outF) {
    constexpr int Kd = (EPI == 2) ? HID : DIMV;
    constexpr int NCH = Kd / 32;
    const __half* A   = (EPI == 2) ? g_h : g_act;
    const __half* Bhi = (EPI == 0) ? g_wqkv_hi : (EPI == 1) ? g_w1_hi : g_w2_hi;
    const __half* Blo = (EPI == 0) ? g_wqkv_lo : (EPI == 1) ? g_w1_lo : g_w2_lo;

    const int tid = threadIdx.x;
    const int lane = tid & 31, wid = tid >> 5;
    const int wm = wid >> 2, wn = wid & 3;      // 2 x 4 warp grid; warp tile 64 x 64
    const int bx = blockIdx.x, by = blockIdx.y;
    const uint32_t smb = smem_u32(dyn_smem);

    auto load_stage = [&](int c, int st) {
        uint32_t sb = smb + st * ST_SIZE;
        // A: 128 rows x 64B = 512 cp16 (2/thread)
        #pragma unroll
        for (int j = 0; j < 2; ++j) {
            int id = tid + 256 * j;
            int r = id >> 2, q = id & 3;
            cp16(sb + r * 80 + q * 16, A + (size_t)(by * 128 + r) * Kd + c * 32 + q * 8);
        }
        // Bhi, Blo: 256 rows x 64B = 1024 cp16 each (4/thread)
        #pragma unroll
        for (int s = 0; s < 2; ++s) {
            const __half* src = s ? Blo : Bhi;
            #pragma unroll
            for (int j = 0; j < 4; ++j) {
                int id = tid + 256 * j;
                int r = id >> 2, q = id & 3;
                cp16(sb + ST_A + s * ST_B + r * 80 + q * 16,
                     src + (size_t)(bx * 256 + r) * Kd + c * 32 + q * 8);
            }
        }
        CP_COMMIT();
    };

    float acc[4][8][4];
    #pragma unroll
    for (int mi = 0; mi < 4; ++mi)
        #pragma unroll
        for (int ni = 0; ni < 8; ++ni)
            #pragma unroll
            for (int r = 0; r < 4; ++r) acc[mi][ni][r] = 0.f;

    load_stage(0, 0);
    load_stage(1, 1);
    load_stage(2, 2);

    for (int c = 0; c < NCH; ++c) {
        CP_WAIT(2);                              // group c complete
        __syncthreads();                         // stage c visible; buf (c+3)&3 free
        if (c + 3 < NCH) load_stage(c + 3, (c + 3) & 3);

        const uint32_t sb = smb + (c & 3) * ST_SIZE;
        #pragma unroll
        for (int ks = 0; ks < 2; ++ks) {
            // B frags: ldsm_x4 covers 2 adjacent ni (matrices: [ni k0][ni k1][ni+1 k0][ni+1 k1])
            uint32_t bhi[8][2], blo[8][2];
            #pragma unroll
            for (int nb = 0; nb < 4; ++nb) {
                int g = lane >> 3;
                uint32_t bd = sb + ST_A + (uint32_t)(wn * 64 + nb * 16 + (g >> 1) * 8 + (lane & 7)) * 80
                            + ks * 32 + (g & 1) * 16;
                uint32_t t[4];
                ldsm_x4(t, bd);
                bhi[2 * nb][0] = t[0]; bhi[2 * nb][1] = t[1];
                bhi[2 * nb + 1][0] = t[2]; bhi[2 * nb + 1][1] = t[3];
                ldsm_x4(t, bd + ST_B);
                blo[2 * nb][0] = t[0]; blo[2 * nb][1] = t[1];
                blo[2 * nb + 1][0] = t[2]; blo[2 * nb + 1][1] = t[3];
            }
            #pragma unroll
            for (int mi = 0; mi < 4; ++mi) {
                uint32_t a[4];
                uint32_t ad = sb + (uint32_t)(wm * 64 + mi * 16 + (lane & 15)) * 80
                            + ks * 32 + (lane >> 4) * 16;
                ldsm_x4(a, ad);
                #pragma unroll
                for (int ni = 0; ni < 8; ++ni) {
                    mma16816h(acc[mi][ni], a, bhi[ni]);
                    mma16816h(acc[mi][ni], a, blo[ni]);
                }
            }
        }
    }

    // ---------------- epilogue ----------------
    const int r0 = lane >> 2, c0 = 2 * (lane & 3);
    #pragma unroll
    for (int mi = 0; mi < 4; ++mi) {
        #pragma unroll
        for (int hh = 0; hh < 2; ++hh) {
            const int grow = by * 128 + wm * 64 + mi * 16 + r0 + hh * 8;
            #pragma unroll
            for (int ni = 0; ni < 8; ++ni) {
                const int gcol = bx * 256 + wn * 64 + ni * 8 + c0;
                float v0 = acc[mi][ni][2 * hh + 0];
                float v1 = acc[mi][ni][2 * hh + 1];
                if (EPI == 0) {
                    float2 o;
                    o.x = v0 + g_qkvb[gcol];
                    o.y = v1 + g_qkvb[gcol + 1];
                    *(float2*)(g_qkv + (size_t)grow * NQKV + gcol) = o;
                } else if (EPI == 1) {
                    float u0 = v0 + bias[gcol];
                    float u1 = v1 + bias[gcol + 1];
                    float gl0 = 0.5f * u0 * (1.0f + erff(u0 * 0.70710678118654752440f));
                    float gl1 = 0.5f * u1 * (1.0f + erff(u1 * 0.70710678118654752440f));
                    size_t idx = (size_t)grow * HID + gcol;
                    *(__half2*)(g_h + idx) = __half2(__float2half(gl0), __float2half(gl1));
                } else {
                    size_t idx = (size_t)grow * DIMV + gcol;
                    float2 res = *(const float2*)(g_y + idx);
                    float2 o;
                    o.x = v0 + bias[gcol] + res.x;
                    o.y = v1 + bias[gcol + 1] + res.y;
                    *(float2*)(outF + idx) = o;
                }
            }
        }
    }
}

// ---------------- launch ----------------
#define ATTN_SMEM (2 * 8 * DIMV * (int)sizeof(float))

extern "C" void kernel_launch(void* const* d_in, const int* in_sizes, int n_in,
                              void* d_out, int out_size) {
    const float* x    = (const float*)d_in[0];
    const float* wq_w = (const float*)d_in[1];
    const float* wq_b = (const float*)d_in[2];
    const float* wk_w = (const float*)d_in[3];
    const float* wk_b = (const float*)d_in[4];
    const float* wv_w = (const float*)d_in[5];
    const float* wv_b = (const float*)d_in[6];
    const float* d1_w = (const float*)d_in[7];
    const float* d1_b = (const float*)d_in[8];
    const float* d2_w = (const float*)d_in[9];
    const float* d2_b = (const float*)d_in[10];
    const float* g1   = (const float*)d_in[11];
    const float* b1   = (const float*)d_in[12];
    const float* g2   = (const float*)d_in[13];
    const float* b2   = (const float*)d_in[14];
    float* out = (float*)d_out;

    cudaFuncSetAttribute(gemm_k<0>, cudaFuncAttributeMaxDynamicSharedMemorySize, GEMM_SMEM);
    cudaFuncSetAttribute(gemm_k<1>, cudaFuncAttributeMaxDynamicSharedMemorySize, GEMM_SMEM);
    cudaFuncSetAttribute(gemm_k<2>, cudaFuncAttributeMaxDynamicSharedMemorySize, GEMM_SMEM);
    cudaFuncSetAttribute(attn_ln2_kernel, cudaFuncAttributeMaxDynamicSharedMemorySize, ATTN_SMEM);

    // launch order chosen so ncu (-s 5 -c 1) profiles gemm_k<1>, the largest GEMM
    prep_qkv<<<2048, 256>>>(wq_w, wk_w, wv_w, wq_b, wk_b, wv_b);       // 0
    prep_mlp<<<4096, 256>>>(d1_w, d2_w);                               // 1
    ln1_kernel<<<TTOK / 8, 256>>>(x, g1, b1);                          // 2
    gemm_k<0><<<dim3(NQKV / 256, TTOK / 128), 256, GEMM_SMEM>>>(nullptr, nullptr);  // 3
    attn_ln2_kernel<<<TTOK / 8, 256, ATTN_SMEM>>>(x, g2, b2);          // 4
    gemm_k<1><<<dim3(HID / 256, TTOK / 128), 256, GEMM_SMEM>>>(d1_b, nullptr);      // 5 <- profiled
    gemm_k<2><<<dim3(DIMV / 256, TTOK / 128), 256, GEMM_SMEM>>>(d2_b, out);         // 6
}

// round 7
// speedup vs baseline: 1.5613x; 1.1342x over previous
#include <cuda_runtime.h>
#include <cuda_bf16.h>
#include <cuda_fp16.h>
#include <cstdint>

#define DIMV 768
#define TTOK 16384
#define HID  3072
#define NQKV 2304

// ---------------- device scratch (allocation-free rule: __device__ globals) -------------
__device__ __align__(256) __half g_act[(size_t)TTOK * DIMV];
__device__ __align__(256) float  g_qkv[(size_t)TTOK * NQKV];
__device__ __align__(256) float  g_y[(size_t)TTOK * DIMV];
__device__ __align__(256) __half g_h[(size_t)TTOK * HID];
__device__ __align__(256) __half g_wqkv_hi[(size_t)NQKV * DIMV];
__device__ __align__(256) __half g_wqkv_lo[(size_t)NQKV * DIMV];
__device__ __align__(256) __half g_w1_hi[(size_t)HID * DIMV];
__device__ __align__(256) __half g_w1_lo[(size_t)HID * DIMV];
__device__ __align__(256) __half g_w2_hi[(size_t)DIMV * HID];
__device__ __align__(256) __half g_w2_lo[(size_t)DIMV * HID];
__device__ __align__(256) float  g_qkvb[NQKV];

extern __shared__ char dyn_smem[];

// ---------------- PTX helpers ----------------
__device__ __forceinline__ uint32_t smem_u32(const void* p) {
    uint32_t a;
    asm("{ .reg .u64 t; cvta.to.shared.u64 t, %1; cvt.u32.u64 %0, t; }" : "=r"(a) : "l"(p));
    return a;
}
__device__ __forceinline__ void cp16(uint32_t smaddr, const void* g) {
    asm volatile("cp.async.cg.shared.global [%0], [%1], 16;" :: "r"(smaddr), "l"(g) : "memory");
}
#define CP_COMMIT() asm volatile("cp.async.commit_group;" ::: "memory")
#define CP_WAIT(n)  asm volatile("cp.async.wait_group %0;" :: "n"(n) : "memory")

__device__ __forceinline__ void ldsm_x4(uint32_t* r, uint32_t addr) {
    asm volatile("ldmatrix.sync.aligned.m8n8.x4.shared.b16 {%0,%1,%2,%3}, [%4];"
                 : "=r"(r[0]), "=r"(r[1]), "=r"(r[2]), "=r"(r[3]) : "r"(addr));
}
__device__ __forceinline__ void mma16816h(float* c, const uint32_t* a, const uint32_t* b) {
    asm volatile("mma.sync.aligned.m16n8k16.row.col.f32.f16.f16.f32 "
                 "{%0,%1,%2,%3}, {%4,%5,%6,%7}, {%8,%9}, {%0,%1,%2,%3};"
                 : "+f"(c[0]), "+f"(c[1]), "+f"(c[2]), "+f"(c[3])
                 : "r"(a[0]), "r"(a[1]), "r"(a[2]), "r"(a[3]), "r"(b[0]), "r"(b[1]));
}

// ---------------- small helpers ----------------
__device__ __forceinline__ float warp_sum(float v) {
    #pragma unroll
    for (int o = 16; o > 0; o >>= 1) v += __shfl_xor_sync(0xffffffffu, v, o);
    return v;
}

// ---------------- prep kernels ----------------
__global__ void prep_qkv(const float* __restrict__ wq, const float* __restrict__ wk,
                         const float* __restrict__ wv, const float* __restrict__ bq,
                         const float* __restrict__ bk, const float* __restrict__ bv) {
    const int n = DIMV * DIMV;
    for (int i = blockIdx.x * blockDim.x + threadIdx.x; i < 3 * n + NQKV; i += gridDim.x * blockDim.x) {
        if (i < 3 * n) {
            int s = i / n, j = i - s * n;
            const float* w = (s == 0) ? wq : (s == 1) ? wk : wv;
            float v = w[j];
            __half h = __float2half(v);
            g_wqkv_hi[(size_t)s * n + j] = h;
            g_wqkv_lo[(size_t)s * n + j] = __float2half(v - __half2float(h));
        } else {
            int j = i - 3 * n;
            g_qkvb[j] = (j < 768) ? bq[j] : (j < 1536) ? bk[j - 768] : bv[j - 1536];
        }
    }
}
__global__ void prep_mlp(const float* __restrict__ d1, const float* __restrict__ d2) {
    const int n = HID * DIMV;
    for (int i = blockIdx.x * blockDim.x + threadIdx.x; i < 2 * n; i += gridDim.x * blockDim.x) {
        if (i < n) {
            float v = d1[i];
            __half h = __float2half(v);
            g_w1_hi[i] = h;
            g_w1_lo[i] = __float2half(v - __half2float(h));
        } else {
            int j = i - n;
            float v = d2[j];
            __half h = __float2half(v);
            g_w2_hi[j] = h;
            g_w2_lo[j] = __float2half(v - __half2float(h));
        }
    }
}

// ---------------- LN1: x -> fp16(layernorm(x)) ; warp per token ----------------
__global__ void ln1_kernel(const float* __restrict__ x, const float* __restrict__ g1,
                           const float* __restrict__ b1) {
    int wid = threadIdx.x >> 5, lid = threadIdx.x & 31;
    int tok = blockIdx.x * 8 + wid;
    const float* xr = x + (size_t)tok * DIMV;
    float xv[24];
    #pragma unroll
    for (int j = 0; j < 24; ++j) xv[j] = xr[lid + 32 * j];
    float s = 0.f;
    #pragma unroll
    for (int j = 0; j < 24; ++j) s += xv[j];
    float mean = warp_sum(s) * (1.0f / DIMV);
    float s2 = 0.f;
    #pragma unroll
    for (int j = 0; j < 24; ++j) { float d = xv[j] - mean; s2 += d * d; }
    float var = warp_sum(s2) * (1.0f / (DIMV - 1));
    float inv = g1[0] / (sqrtf(var) + 1e-6f);
    float bb = b1[0];
    size_t base = (size_t)tok * DIMV;
    #pragma unroll
    for (int j = 0; j < 24; ++j)
        g_act[base + lid + 32 * j] = __float2half((xv[j] - mean) * inv + bb);
}

// ---------------- attention + residual + LN2 ----------------
__global__ void attn_ln2_kernel(const float* __restrict__ x, const float* __restrict__ g2,
                                const float* __restrict__ b2) {
    float* ks = (float*)dyn_smem;
    float* vs = ks + 8 * DIMV;
    int tid = threadIdx.x;
    int wid = tid >> 5, lid = tid & 31;
    int t0 = blockIdx.x * 8;
    for (int i = tid; i < 8 * DIMV; i += 256) {
        int r = i / DIMV, c = i - r * DIMV;
        const float* row = g_qkv + (size_t)(t0 + r) * NQKV;
        ks[i] = row[768 + c];
        vs[i] = row[1536 + c];
    }
    __syncthreads();
    int h = wid;
    const float* qr = g_qkv + (size_t)(t0 + h) * NQKV;
    float qv[24];
    #pragma unroll
    for (int j = 0; j < 24; ++j) qv[j] = qr[lid + 32 * j];
    float p[8];
    #pragma unroll
    for (int kk = 0; kk < 8; ++kk) {
        float acc = 0.f;
        const float* kr = ks + kk * DIMV;
        #pragma unroll
        for (int j = 0; j < 24; ++j) acc += qv[j] * kr[lid + 32 * j];
        p[kk] = acc;
    }
    #pragma unroll
    for (int kk = 0; kk < 8; ++kk) p[kk] = warp_sum(p[kk]) * 0.03608439182435161f;
    float m = p[0];
    #pragma unroll
    for (int kk = 1; kk < 8; ++kk) m = fmaxf(m, p[kk]);
    float se = 0.f;
    #pragma unroll
    for (int kk = 0; kk < 8; ++kk) { p[kk] = __expf(p[kk] - m); se += p[kk]; }
    float rinv = 1.0f / se;
    #pragma unroll
    for (int kk = 0; kk < 8; ++kk) p[kk] *= rinv;
    const float* xr = x + (size_t)(t0 + h) * DIMV;
    float yv[24];
    #pragma unroll
    for (int j = 0; j < 24; ++j) {
        int d = lid + 32 * j;
        float a = 0.f;
        #pragma unroll
        for (int kk = 0; kk < 8; ++kk) a += p[kk] * vs[kk * DIMV + d];
        yv[j] = a + xr[d];
    }
    size_t base = (size_t)(t0 + h) * DIMV;
    #pragma unroll
    for (int j = 0; j < 24; ++j) g_y[base + lid + 32 * j] = yv[j];
    float s = 0.f;
    #pragma unroll
    for (int j = 0; j < 24; ++j) s += yv[j];
    float mean = warp_sum(s) * (1.0f / DIMV);
    float s2 = 0.f;
    #pragma unroll
    for (int j = 0; j < 24; ++j) { float d = yv[j] - mean; s2 += d * d; }
    float var = warp_sum(s2) * (1.0f / (DIMV - 1));
    float inv = g2[0] / (sqrtf(var) + 1e-6f);
    float bb = b2[0];
    #pragma unroll
    for (int j = 0; j < 24; ++j)
        g_act[base + lid + 32 * j] = __float2half((yv[j] - mean) * inv + bb);
}

// ---------------- fp16 mma GEMM: 128x128 tile, 8 warps (2x4, warp 64x32), 2 CTAs/SM -----
// A single fp16, B split hi/lo -> 2 MMAs per k16.
// Stage: A(128x80B) + Bhi(128x80B) + Blo(128x80B) = 30720 B; 3 stages = 92160 B.
#define ST_A    10240
#define ST_B    10240
#define ST_SIZE 30720
#define N_STAGE 3
#define GEMM_SMEM (N_STAGE * ST_SIZE)

// EPI 0: act @ wqkv^T + qkvb  -> g_qkv          (K=768,  N=2304)
// EPI 1: act @ w1^T + d1_b, gelu -> g_h (fp16)  (K=768,  N=3072)
// EPI 2: h @ w2^T + d2_b + g_y -> outF          (K=3072, N=768)
template <int EPI>
__global__ void __launch_bounds__(256, 2) gemm_k(const float* __restrict__ bias, float* __restrict__ outF) {
    constexpr int Kd = (EPI == 2) ? HID : DIMV;
    constexpr int NCH = Kd / 32;
    const __half* A   = (EPI == 2) ? g_h : g_act;
    const __half* Bhi = (EPI == 0) ? g_wqkv_hi : (EPI == 1) ? g_w1_hi : g_w2_hi;
    const __half* Blo = (EPI == 0) ? g_wqkv_lo : (EPI == 1) ? g_w1_lo : g_w2_lo;

    const int tid = threadIdx.x;
    const int lane = tid & 31, wid = tid >> 5;
    const int wm = wid >> 2, wn = wid & 3;      // 2 x 4 warp grid; warp tile 64 x 32
    const int bx = blockIdx.x, by = blockIdx.y;
    const uint32_t smb = smem_u32(dyn_smem);

    auto load_stage = [&](int c, int st) {
        uint32_t sb = smb + st * ST_SIZE;
        // A: 128 rows x 64B = 512 cp16 (2/thread)
        #pragma unroll
        for (int j = 0; j < 2; ++j) {
            int id = tid + 256 * j;
            int r = id >> 2, q = id & 3;
            cp16(sb + r * 80 + q * 16, A + (size_t)(by * 128 + r) * Kd + c * 32 + q * 8);
        }
        // Bhi, Blo: 128 rows x 64B = 512 cp16 each (2/thread)
        #pragma unroll
        for (int s = 0; s < 2; ++s) {
            const __half* src = s ? Blo : Bhi;
            #pragma unroll
            for (int j = 0; j < 2; ++j) {
                int id = tid + 256 * j;
                int r = id >> 2, q = id & 3;
                cp16(sb + ST_A + s * ST_B + r * 80 + q * 16,
                     src + (size_t)(bx * 128 + r) * Kd + c * 32 + q * 8);
            }
        }
        CP_COMMIT();
    };

    float acc[4][4][4];
    #pragma unroll
    for (int mi = 0; mi < 4; ++mi)
        #pragma unroll
        for (int ni = 0; ni < 4; ++ni)
            #pragma unroll
            for (int r = 0; r < 4; ++r) acc[mi][ni][r] = 0.f;

    load_stage(0, 0);
    load_stage(1, 1);

    for (int c = 0; c < NCH; ++c) {
        CP_WAIT(1);                              // group c complete
        __syncthreads();                         // stage c visible; buf (c+2)%3 free
        if (c + 2 < NCH) load_stage(c + 2, (c + 2) % N_STAGE);

        const uint32_t sb = smb + (c % N_STAGE) * ST_SIZE;
        #pragma unroll
        for (int ks = 0; ks < 2; ++ks) {
            // B frags: ldsm_x4 covers 2 adjacent ni
            uint32_t bhi[4][2], blo[4][2];
            #pragma unroll
            for (int nb = 0; nb < 2; ++nb) {
                int g = lane >> 3;
                uint32_t bd = sb + ST_A + (uint32_t)(wn * 32 + nb * 16 + (g >> 1) * 8 + (lane & 7)) * 80
                            + ks * 32 + (g & 1) * 16;
                uint32_t t[4];
                ldsm_x4(t, bd);
                bhi[2 * nb][0] = t[0]; bhi[2 * nb][1] = t[1];
                bhi[2 * nb + 1][0] = t[2]; bhi[2 * nb + 1][1] = t[3];
                ldsm_x4(t, bd + ST_B);
                blo[2 * nb][0] = t[0]; blo[2 * nb][1] = t[1];
                blo[2 * nb + 1][0] = t[2]; blo[2 * nb + 1][1] = t[3];
            }
            #pragma unroll
            for (int mi = 0; mi < 4; ++mi) {
                uint32_t a[4];
                uint32_t ad = sb + (uint32_t)(wm * 64 + mi * 16 + (lane & 15)) * 80
                            + ks * 32 + (lane >> 4) * 16;
                ldsm_x4(a, ad);
                #pragma unroll
                for (int ni = 0; ni < 4; ++ni) {
                    mma16816h(acc[mi][ni], a, bhi[ni]);
                    mma16816h(acc[mi][ni], a, blo[ni]);
                }
            }
        }
    }

    // ---------------- epilogue ----------------
    const int r0 = lane >> 2, c0 = 2 * (lane & 3);
    #pragma unroll
    for (int mi = 0; mi < 4; ++mi) {
        #pragma unroll
        for (int hh = 0; hh < 2; ++hh) {
            const int grow = by * 128 + wm * 64 + mi * 16 + r0 + hh * 8;
            #pragma unroll
            for (int ni = 0; ni < 4; ++ni) {
                const int gcol = bx * 128 + wn * 32 + ni * 8 + c0;
                float v0 = acc[mi][ni][2 * hh + 0];
                float v1 = acc[mi][ni][2 * hh + 1];
                if (EPI == 0) {
                    float2 o;
                    o.x = v0 + g_qkvb[gcol];
                    o.y = v1 + g_qkvb[gcol + 1];
                    *(float2*)(g_qkv + (size_t)grow * NQKV + gcol) = o;
                } else if (EPI == 1) {
                    float u0 = v0 + bias[gcol];
                    float u1 = v1 + bias[gcol + 1];
                    float gl0 = 0.5f * u0 * (1.0f + erff(u0 * 0.70710678118654752440f));
                    float gl1 = 0.5f * u1 * (1.0f + erff(u1 * 0.70710678118654752440f));
                    size_t idx = (size_t)grow * HID + gcol;
                    *(__half2*)(g_h + idx) = __half2(__float2half(gl0), __float2half(gl1));
                } else {
                    size_t idx = (size_t)grow * DIMV + gcol;
                    float2 res = *(const float2*)(g_y + idx);
                    float2 o;
                    o.x = v0 + bias[gcol] + res.x;
                    o.y = v1 + bias[gcol + 1] + res.y;
                    *(float2*)(outF + idx) = o;
                }
            }
        }
    }
}

// ---------------- launch ----------------
#define ATTN_SMEM (2 * 8 * DIMV * (int)sizeof(float))

extern "C" void kernel_launch(void* const* d_in, const int* in_sizes, int n_in,
                              void* d_out, int out_size) {
    const float* x    = (const float*)d_in[0];
    const float* wq_w = (const float*)d_in[1];
    const float* wq_b = (const float*)d_in[2];
    const float* wk_w = (const float*)d_in[3];
    const float* wk_b = (const float*)d_in[4];
    const float* wv_w = (const float*)d_in[5];
    const float* wv_b = (const float*)d_in[6];
    const float* d1_w = (const float*)d_in[7];
    const float* d1_b = (const float*)d_in[8];
    const float* d2_w = (const float*)d_in[9];
    const float* d2_b = (const float*)d_in[10];
    const float* g1   = (const float*)d_in[11];
    const float* b1   = (const float*)d_in[12];
    const float* g2   = (const float*)d_in[13];
    const float* b2   = (const float*)d_in[14];
    float* out = (float*)d_out;

    cudaFuncSetAttribute(gemm_k<0>, cudaFuncAttributeMaxDynamicSharedMemorySize, GEMM_SMEM);
    cudaFuncSetAttribute(gemm_k<1>, cudaFuncAttributeMaxDynamicSharedMemorySize, GEMM_SMEM);
    cudaFuncSetAttribute(gemm_k<2>, cudaFuncAttributeMaxDynamicSharedMemorySize, GEMM_SMEM);
    cudaFuncSetAttribute(attn_ln2_kernel, cudaFuncAttributeMaxDynamicSharedMemorySize, ATTN_SMEM);

    // launch order chosen so ncu (-s 5 -c 1) profiles gemm_k<1>, the largest GEMM
    prep_qkv<<<2048, 256>>>(wq_w, wk_w, wv_w, wq_b, wk_b, wv_b);       // 0
    prep_mlp<<<4096, 256>>>(d1_w, d2_w);                               // 1
    ln1_kernel<<<TTOK / 8, 256>>>(x, g1, b1);                          // 2
    gemm_k<0><<<dim3(NQKV / 128, TTOK / 128), 256, GEMM_SMEM>>>(nullptr, nullptr);  // 3
    attn_ln2_kernel<<<TTOK / 8, 256, ATTN_SMEM>>>(x, g2, b2);          // 4
    gemm_k<1><<<dim3(HID / 128, TTOK / 128), 256, GEMM_SMEM>>>(d1_b, nullptr);      // 5 <- profiled
    gemm_k<2><<<dim3(DIMV / 128, TTOK / 128), 256, GEMM_SMEM>>>(d2_b, out);         // 6
}

// round 8
// speedup vs baseline: 2.4151x; 1.5468x over previous
#include <cuda_runtime.h>
#include <cuda_bf16.h>
#include <cuda_fp16.h>
#include <cstdint>

#define DIMV 768
#define TTOK 16384
#define HID  3072
#define NQKV 2304

// ---------------- device scratch (allocation-free rule: __device__ globals) -------------
__device__ __align__(256) __half g_act[(size_t)TTOK * DIMV];
__device__ __align__(256) float  g_qkv[(size_t)TTOK * NQKV];
__device__ __align__(256) float  g_y[(size_t)TTOK * DIMV];
__device__ __align__(256) __half g_h[(size_t)TTOK * HID];
__device__ __align__(256) __half g_wqkv[(size_t)NQKV * DIMV];
__device__ __align__(256) __half g_w1[(size_t)HID * DIMV];
__device__ __align__(256) __half g_w2[(size_t)DIMV * HID];
__device__ __align__(256) float  g_qkvb[NQKV];

extern __shared__ char dyn_smem[];

// ---------------- PTX helpers ----------------
__device__ __forceinline__ uint32_t smem_u32(const void* p) {
    uint32_t a;
    asm("{ .reg .u64 t; cvta.to.shared.u64 t, %1; cvt.u32.u64 %0, t; }" : "=r"(a) : "l"(p));
    return a;
}
__device__ __forceinline__ void cp16(uint32_t smaddr, const void* g) {
    asm volatile("cp.async.cg.shared.global [%0], [%1], 16;" :: "r"(smaddr), "l"(g) : "memory");
}
#define CP_COMMIT() asm volatile("cp.async.commit_group;" ::: "memory")
#define CP_WAIT(n)  asm volatile("cp.async.wait_group %0;" :: "n"(n) : "memory")

__device__ __forceinline__ void ldsm_x4(uint32_t* r, uint32_t addr) {
    asm volatile("ldmatrix.sync.aligned.m8n8.x4.shared.b16 {%0,%1,%2,%3}, [%4];"
                 : "=r"(r[0]), "=r"(r[1]), "=r"(r[2]), "=r"(r[3]) : "r"(addr));
}
__device__ __forceinline__ void mma16816h(float* c, const uint32_t* a, const uint32_t* b) {
    asm volatile("mma.sync.aligned.m16n8k16.row.col.f32.f16.f16.f32 "
                 "{%0,%1,%2,%3}, {%4,%5,%6,%7}, {%8,%9}, {%0,%1,%2,%3};"
                 : "+f"(c[0]), "+f"(c[1]), "+f"(c[2]), "+f"(c[3])
                 : "r"(a[0]), "r"(a[1]), "r"(a[2]), "r"(a[3]), "r"(b[0]), "r"(b[1]));
}

// ---------------- small helpers ----------------
__device__ __forceinline__ float warp_sum(float v) {
    #pragma unroll
    for (int o = 16; o > 0; o >>= 1) v += __shfl_xor_sync(0xffffffffu, v, o);
    return v;
}

// ---------------- prep kernels ----------------
__global__ void prep_qkv(const float* __restrict__ wq, const float* __restrict__ wk,
                         const float* __restrict__ wv, const float* __restrict__ bq,
                         const float* __restrict__ bk, const float* __restrict__ bv) {
    const int n = DIMV * DIMV;
    for (int i = blockIdx.x * blockDim.x + threadIdx.x; i < 3 * n + NQKV; i += gridDim.x * blockDim.x) {
        if (i < 3 * n) {
            int s = i / n, j = i - s * n;
            const float* w = (s == 0) ? wq : (s == 1) ? wk : wv;
            g_wqkv[(size_t)s * n + j] = __float2half(w[j]);
        } else {
            int j = i - 3 * n;
            g_qkvb[j] = (j < 768) ? bq[j] : (j < 1536) ? bk[j - 768] : bv[j - 1536];
        }
    }
}
__global__ void prep_mlp(const float* __restrict__ d1, const float* __restrict__ d2) {
    const int n = HID * DIMV;
    for (int i = blockIdx.x * blockDim.x + threadIdx.x; i < 2 * n; i += gridDim.x * blockDim.x) {
        if (i < n) g_w1[i] = __float2half(d1[i]);
        else       g_w2[i - n] = __float2half(d2[i - n]);
    }
}

// ---------------- LN1: x -> fp16(layernorm(x)) ; warp per token ----------------
__global__ void ln1_kernel(const float* __restrict__ x, const float* __restrict__ g1,
                           const float* __restrict__ b1) {
    int wid = threadIdx.x >> 5, lid = threadIdx.x & 31;
    int tok = blockIdx.x * 8 + wid;
    const float* xr = x + (size_t)tok * DIMV;
    float xv[24];
    #pragma unroll
    for (int j = 0; j < 24; ++j) xv[j] = xr[lid + 32 * j];
    float s = 0.f;
    #pragma unroll
    for (int j = 0; j < 24; ++j) s += xv[j];
    float mean = warp_sum(s) * (1.0f / DIMV);
    float s2 = 0.f;
    #pragma unroll
    for (int j = 0; j < 24; ++j) { float d = xv[j] - mean; s2 += d * d; }
    float var = warp_sum(s2) * (1.0f / (DIMV - 1));
    float inv = g1[0] / (sqrtf(var) + 1e-6f);
    float bb = b1[0];
    size_t base = (size_t)tok * DIMV;
    #pragma unroll
    for (int j = 0; j < 24; ++j)
        g_act[base + lid + 32 * j] = __float2half((xv[j] - mean) * inv + bb);
}

// ---------------- attention + residual + LN2 ----------------
__global__ void attn_ln2_kernel(const float* __restrict__ x, const float* __restrict__ g2,
                                const float* __restrict__ b2) {
    float* ks = (float*)dyn_smem;
    float* vs = ks + 8 * DIMV;
    int tid = threadIdx.x;
    int wid = tid >> 5, lid = tid & 31;
    int t0 = blockIdx.x * 8;
    for (int i = tid; i < 8 * DIMV; i += 256) {
        int r = i / DIMV, c = i - r * DIMV;
        const float* row = g_qkv + (size_t)(t0 + r) * NQKV;
        ks[i] = row[768 + c];
        vs[i] = row[1536 + c];
    }
    __syncthreads();
    int h = wid;
    const float* qr = g_qkv + (size_t)(t0 + h) * NQKV;
    float qv[24];
    #pragma unroll
    for (int j = 0; j < 24; ++j) qv[j] = qr[lid + 32 * j];
    float p[8];
    #pragma unroll
    for (int kk = 0; kk < 8; ++kk) {
        float acc = 0.f;
        const float* kr = ks + kk * DIMV;
        #pragma unroll
        for (int j = 0; j < 24; ++j) acc += qv[j] * kr[lid + 32 * j];
        p[kk] = acc;
    }
    #pragma unroll
    for (int kk = 0; kk < 8; ++kk) p[kk] = warp_sum(p[kk]) * 0.03608439182435161f;
    float m = p[0];
    #pragma unroll
    for (int kk = 1; kk < 8; ++kk) m = fmaxf(m, p[kk]);
    float se = 0.f;
    #pragma unroll
    for (int kk = 0; kk < 8; ++kk) { p[kk] = __expf(p[kk] - m); se += p[kk]; }
    float rinv = 1.0f / se;
    #pragma unroll
    for (int kk = 0; kk < 8; ++kk) p[kk] *= rinv;
    const float* xr = x + (size_t)(t0 + h) * DIMV;
    float yv[24];
    #pragma unroll
    for (int j = 0; j < 24; ++j) {
        int d = lid + 32 * j;
        float a = 0.f;
        #pragma unroll
        for (int kk = 0; kk < 8; ++kk) a += p[kk] * vs[kk * DIMV + d];
        yv[j] = a + xr[d];
    }
    size_t base = (size_t)(t0 + h) * DIMV;
    #pragma unroll
    for (int j = 0; j < 24; ++j) g_y[base + lid + 32 * j] = yv[j];
    float s = 0.f;
    #pragma unroll
    for (int j = 0; j < 24; ++j) s += yv[j];
    float mean = warp_sum(s) * (1.0f / DIMV);
    float s2 = 0.f;
    #pragma unroll
    for (int j = 0; j < 24; ++j) { float d = yv[j] - mean; s2 += d * d; }
    float var = warp_sum(s2) * (1.0f / (DIMV - 1));
    float inv = g2[0] / (sqrtf(var) + 1e-6f);
    float bb = b2[0];
    #pragma unroll
    for (int j = 0; j < 24; ++j)
        g_act[base + lid + 32 * j] = __float2half((yv[j] - mean) * inv + bb);
}

// ---------------- fp16 single-pass GEMM: 128x128 tile, 8 warps (2x4, warp 64x32) --------
// 2 CTAs/SM. Stage: A(128x80B) + B(128x80B) = 20480 B; 4 stages = 81920 B.
#define ST_A    10240
#define ST_SIZE 20480
#define N_STAGE 4
#define GEMM_SMEM (N_STAGE * ST_SIZE)

// EPI 0: act @ wqkv^T + qkvb  -> g_qkv          (K=768,  N=2304)
// EPI 1: act @ w1^T + d1_b, gelu -> g_h (fp16)  (K=768,  N=3072)
// EPI 2: h @ w2^T + d2_b + g_y -> outF          (K=3072, N=768)
template <int EPI>
__global__ void __launch_bounds__(256, 2) gemm_k(const float* __restrict__ bias, float* __restrict__ outF) {
    constexpr int Kd = (EPI == 2) ? HID : DIMV;
    constexpr int NCH = Kd / 32;
    const __half* A = (EPI == 2) ? g_h : g_act;
    const __half* B = (EPI == 0) ? g_wqkv : (EPI == 1) ? g_w1 : g_w2;

    const int tid = threadIdx.x;
    const int lane = tid & 31, wid = tid >> 5;
    const int wm = wid >> 2, wn = wid & 3;      // 2 x 4 warp grid; warp tile 64 x 32
    const int bx = blockIdx.x, by = blockIdx.y;
    const uint32_t smb = smem_u32(dyn_smem);

    auto load_stage = [&](int c, int st) {
        uint32_t sb = smb + st * ST_SIZE;
        // A: 128 rows x 64B = 512 cp16 (2/thread)
        #pragma unroll
        for (int j = 0; j < 2; ++j) {
            int id = tid + 256 * j;
            int r = id >> 2, q = id & 3;
            cp16(sb + r * 80 + q * 16, A + (size_t)(by * 128 + r) * Kd + c * 32 + q * 8);
        }
        // B: 128 rows x 64B = 512 cp16 (2/thread)
        #pragma unroll
        for (int j = 0; j < 2; ++j) {
            int id = tid + 256 * j;
            int r = id >> 2, q = id & 3;
            cp16(sb + ST_A + r * 80 + q * 16, B + (size_t)(bx * 128 + r) * Kd + c * 32 + q * 8);
        }
        CP_COMMIT();
    };

    float acc[4][4][4];
    #pragma unroll
    for (int mi = 0; mi < 4; ++mi)
        #pragma unroll
        for (int ni = 0; ni < 4; ++ni)
            #pragma unroll
            for (int r = 0; r < 4; ++r) acc[mi][ni][r] = 0.f;

    load_stage(0, 0);
    load_stage(1, 1);
    load_stage(2, 2);

    for (int c = 0; c < NCH; ++c) {
        CP_WAIT(2);                              // group c complete
        __syncthreads();                         // stage c visible; buf (c+3)&3 free
        if (c + 3 < NCH) load_stage(c + 3, (c + 3) & 3);

        const uint32_t sb = smb + (c & 3) * ST_SIZE;
        #pragma unroll
        for (int ks = 0; ks < 2; ++ks) {
            // B frags: ldsm_x4 covers 2 adjacent ni
            uint32_t bf[4][2];
            #pragma unroll
            for (int nb = 0; nb < 2; ++nb) {
                int g = lane >> 3;
                uint32_t bd = sb + ST_A + (uint32_t)(wn * 32 + nb * 16 + (g >> 1) * 8 + (lane & 7)) * 80
                            + ks * 32 + (g & 1) * 16;
                uint32_t t[4];
                ldsm_x4(t, bd);
                bf[2 * nb][0] = t[0]; bf[2 * nb][1] = t[1];
                bf[2 * nb + 1][0] = t[2]; bf[2 * nb + 1][1] = t[3];
            }
            #pragma unroll
            for (int mi = 0; mi < 4; ++mi) {
                uint32_t a[4];
                uint32_t ad = sb + (uint32_t)(wm * 64 + mi * 16 + (lane & 15)) * 80
                            + ks * 32 + (lane >> 4) * 16;
                ldsm_x4(a, ad);
                #pragma unroll
                for (int ni = 0; ni < 4; ++ni)
                    mma16816h(acc[mi][ni], a, bf[ni]);
            }
        }
    }

    // ---------------- epilogue ----------------
    const int r0 = lane >> 2, c0 = 2 * (lane & 3);
    #pragma unroll
    for (int mi = 0; mi < 4; ++mi) {
        #pragma unroll
        for (int hh = 0; hh < 2; ++hh) {
            const int grow = by * 128 + wm * 64 + mi * 16 + r0 + hh * 8;
            #pragma unroll
            for (int ni = 0; ni < 4; ++ni) {
                const int gcol = bx * 128 + wn * 32 + ni * 8 + c0;
                float v0 = acc[mi][ni][2 * hh + 0];
                float v1 = acc[mi][ni][2 * hh + 1];
                if (EPI == 0) {
                    float2 o;
                    o.x = v0 + g_qkvb[gcol];
                    o.y = v1 + g_qkvb[gcol + 1];
                    *(float2*)(g_qkv + (size_t)grow * NQKV + gcol) = o;
                } else if (EPI == 1) {
                    float u0 = v0 + bias[gcol];
                    float u1 = v1 + bias[gcol + 1];
                    float gl0 = 0.5f * u0 * (1.0f + erff(u0 * 0.70710678118654752440f));
                    float gl1 = 0.5f * u1 * (1.0f + erff(u1 * 0.70710678118654752440f));
                    size_t idx = (size_t)grow * HID + gcol;
                    *(__half2*)(g_h + idx) = __half2(__float2half(gl0), __float2half(gl1));
                } else {
                    size_t idx = (size_t)grow * DIMV + gcol;
                    float2 res = *(const float2*)(g_y + idx);
                    float2 o;
                    o.x = v0 + bias[gcol] + res.x;
                    o.y = v1 + bias[gcol + 1] + res.y;
                    *(float2*)(outF + idx) = o;
                }
            }
        }
    }
}

// ---------------- launch ----------------
#define ATTN_SMEM (2 * 8 * DIMV * (int)sizeof(float))

extern "C" void kernel_launch(void* const* d_in, const int* in_sizes, int n_in,
                              void* d_out, int out_size) {
    const float* x    = (const float*)d_in[0];
    const float* wq_w = (const float*)d_in[1];
    const float* wq_b = (const float*)d_in[2];
    const float* wk_w = (const float*)d_in[3];
    const float* wk_b = (const float*)d_in[4];
    const float* wv_w = (const float*)d_in[5];
    const float* wv_b = (const float*)d_in[6];
    const float* d1_w = (const float*)d_in[7];
    const float* d1_b = (const float*)d_in[8];
    const float* d2_w = (const float*)d_in[9];
    const float* d2_b = (const float*)d_in[10];
    const float* g1   = (const float*)d_in[11];
    const float* b1   = (const float*)d_in[12];
    const float* g2   = (const float*)d_in[13];
    const float* b2   = (const float*)d_in[14];
    float* out = (float*)d_out;

    cudaFuncSetAttribute(gemm_k<0>, cudaFuncAttributeMaxDynamicSharedMemorySize, GEMM_SMEM);
    cudaFuncSetAttribute(gemm_k<1>, cudaFuncAttributeMaxDynamicSharedMemorySize, GEMM_SMEM);
    cudaFuncSetAttribute(gemm_k<2>, cudaFuncAttributeMaxDynamicSharedMemorySize, GEMM_SMEM);
    cudaFuncSetAttribute(attn_ln2_kernel, cudaFuncAttributeMaxDynamicSharedMemorySize, ATTN_SMEM);

    // launch order chosen so ncu (-s 5 -c 1) profiles gemm_k<1>, the largest GEMM
    prep_qkv<<<2048, 256>>>(wq_w, wk_w, wv_w, wq_b, wk_b, wv_b);       // 0
    prep_mlp<<<4096, 256>>>(d1_w, d2_w);                               // 1
    ln1_kernel<<<TTOK / 8, 256>>>(x, g1, b1);                          // 2
    gemm_k<0><<<dim3(NQKV / 128, TTOK / 128), 256, GEMM_SMEM>>>(nullptr, nullptr);  // 3
    attn_ln2_kernel<<<TTOK / 8, 256, ATTN_SMEM>>>(x, g2, b2);          // 4
    gemm_k<1><<<dim3(HID / 128, TTOK / 128), 256, GEMM_SMEM>>>(d1_b, nullptr);      // 5 <- profiled
    gemm_k<2><<<dim3(DIMV / 128, TTOK / 128), 256, GEMM_SMEM>>>(d2_b, out);         // 6
}

// round 9
// speedup vs baseline: 2.6819x; 1.1104x over previous
#include <cuda_runtime.h>
#include <cuda_bf16.h>
#include <cuda_fp16.h>
#include <cstdint>

#define DIMV 768
#define TTOK 16384
#define HID  3072
#define NQKV 2304

// ---------------- device scratch (allocation-free rule: __device__ globals) -------------
__device__ __align__(256) __half g_act[(size_t)TTOK * DIMV];
__device__ __align__(256) float  g_qkv[(size_t)TTOK * NQKV];
__device__ __align__(256) float  g_y[(size_t)TTOK * DIMV];
__device__ __align__(256) __half g_h[(size_t)TTOK * HID];
__device__ __align__(256) __half g_wqkv[(size_t)NQKV * DIMV];
__device__ __align__(256) __half g_w1[(size_t)HID * DIMV];
__device__ __align__(256) __half g_w2[(size_t)DIMV * HID];
__device__ __align__(256) float  g_qkvb[NQKV];

extern __shared__ char dyn_smem[];

// ---------------- PTX helpers ----------------
__device__ __forceinline__ uint32_t smem_u32(const void* p) {
    uint32_t a;
    asm("{ .reg .u64 t; cvta.to.shared.u64 t, %1; cvt.u32.u64 %0, t; }" : "=r"(a) : "l"(p));
    return a;
}
__device__ __forceinline__ void cp16(uint32_t smaddr, const void* g) {
    asm volatile("cp.async.cg.shared.global [%0], [%1], 16;" :: "r"(smaddr), "l"(g) : "memory");
}
#define CP_COMMIT() asm volatile("cp.async.commit_group;" ::: "memory")
#define CP_WAIT(n)  asm volatile("cp.async.wait_group %0;" :: "n"(n) : "memory")

__device__ __forceinline__ void ldsm_x4(uint32_t* r, uint32_t addr) {
    asm volatile("ldmatrix.sync.aligned.m8n8.x4.shared.b16 {%0,%1,%2,%3}, [%4];"
                 : "=r"(r[0]), "=r"(r[1]), "=r"(r[2]), "=r"(r[3]) : "r"(addr));
}
__device__ __forceinline__ void mma16816h(float* c, const uint32_t* a, const uint32_t* b) {
    asm volatile("mma.sync.aligned.m16n8k16.row.col.f32.f16.f16.f32 "
                 "{%0,%1,%2,%3}, {%4,%5,%6,%7}, {%8,%9}, {%0,%1,%2,%3};"
                 : "+f"(c[0]), "+f"(c[1]), "+f"(c[2]), "+f"(c[3])
                 : "r"(a[0]), "r"(a[1]), "r"(a[2]), "r"(a[3]), "r"(b[0]), "r"(b[1]));
}

// ---------------- small helpers ----------------
__device__ __forceinline__ float warp_sum(float v) {
    #pragma unroll
    for (int o = 16; o > 0; o >>= 1) v += __shfl_xor_sync(0xffffffffu, v, o);
    return v;
}

// ---------------- prep kernels ----------------
__global__ void prep_qkv(const float* __restrict__ wq, const float* __restrict__ wk,
                         const float* __restrict__ wv, const float* __restrict__ bq,
                         const float* __restrict__ bk, const float* __restrict__ bv) {
    const int n = DIMV * DIMV;
    for (int i = blockIdx.x * blockDim.x + threadIdx.x; i < 3 * n + NQKV; i += gridDim.x * blockDim.x) {
        if (i < 3 * n) {
            int s = i / n, j = i - s * n;
            const float* w = (s == 0) ? wq : (s == 1) ? wk : wv;
            g_wqkv[(size_t)s * n + j] = __float2half(w[j]);
        } else {
            int j = i - 3 * n;
            g_qkvb[j] = (j < 768) ? bq[j] : (j < 1536) ? bk[j - 768] : bv[j - 1536];
        }
    }
}
__global__ void prep_mlp(const float* __restrict__ d1, const float* __restrict__ d2) {
    const int n = HID * DIMV;
    for (int i = blockIdx.x * blockDim.x + threadIdx.x; i < 2 * n; i += gridDim.x * blockDim.x) {
        if (i < n) g_w1[i] = __float2half(d1[i]);
        else       g_w2[i - n] = __float2half(d2[i - n]);
    }
}

// ---------------- LN1: x -> fp16(layernorm(x)) ; warp per token ----------------
__global__ void ln1_kernel(const float* __restrict__ x, const float* __restrict__ g1,
                           const float* __restrict__ b1) {
    int wid = threadIdx.x >> 5, lid = threadIdx.x & 31;
    int tok = blockIdx.x * 8 + wid;
    const float* xr = x + (size_t)tok * DIMV;
    float xv[24];
    #pragma unroll
    for (int j = 0; j < 24; ++j) xv[j] = xr[lid + 32 * j];
    float s = 0.f;
    #pragma unroll
    for (int j = 0; j < 24; ++j) s += xv[j];
    float mean = warp_sum(s) * (1.0f / DIMV);
    float s2 = 0.f;
    #pragma unroll
    for (int j = 0; j < 24; ++j) { float d = xv[j] - mean; s2 += d * d; }
    float var = warp_sum(s2) * (1.0f / (DIMV - 1));
    float inv = g1[0] / (sqrtf(var) + 1e-6f);
    float bb = b1[0];
    size_t base = (size_t)tok * DIMV;
    #pragma unroll
    for (int j = 0; j < 24; ++j)
        g_act[base + lid + 32 * j] = __float2half((xv[j] - mean) * inv + bb);
}

// ---------------- attention + residual + LN2 ----------------
__global__ void attn_ln2_kernel(const float* __restrict__ x, const float* __restrict__ g2,
                                const float* __restrict__ b2) {
    float* ks = (float*)dyn_smem;
    float* vs = ks + 8 * DIMV;
    int tid = threadIdx.x;
    int wid = tid >> 5, lid = tid & 31;
    int t0 = blockIdx.x * 8;
    for (int i = tid; i < 8 * DIMV; i += 256) {
        int r = i / DIMV, c = i - r * DIMV;
        const float* row = g_qkv + (size_t)(t0 + r) * NQKV;
        ks[i] = row[768 + c];
        vs[i] = row[1536 + c];
    }
    __syncthreads();
    int h = wid;
    const float* qr = g_qkv + (size_t)(t0 + h) * NQKV;
    float qv[24];
    #pragma unroll
    for (int j = 0; j < 24; ++j) qv[j] = qr[lid + 32 * j];
    float p[8];
    #pragma unroll
    for (int kk = 0; kk < 8; ++kk) {
        float acc = 0.f;
        const float* kr = ks + kk * DIMV;
        #pragma unroll
        for (int j = 0; j < 24; ++j) acc += qv[j] * kr[lid + 32 * j];
        p[kk] = acc;
    }
    #pragma unroll
    for (int kk = 0; kk < 8; ++kk) p[kk] = warp_sum(p[kk]) * 0.03608439182435161f;
    float m = p[0];
    #pragma unroll
    for (int kk = 1; kk < 8; ++kk) m = fmaxf(m, p[kk]);
    float se = 0.f;
    #pragma unroll
    for (int kk = 0; kk < 8; ++kk) { p[kk] = __expf(p[kk] - m); se += p[kk]; }
    float rinv = 1.0f / se;
    #pragma unroll
    for (int kk = 0; kk < 8; ++kk) p[kk] *= rinv;
    const float* xr = x + (size_t)(t0 + h) * DIMV;
    float yv[24];
    #pragma unroll
    for (int j = 0; j < 24; ++j) {
        int d = lid + 32 * j;
        float a = 0.f;
        #pragma unroll
        for (int kk = 0; kk < 8; ++kk) a += p[kk] * vs[kk * DIMV + d];
        yv[j] = a + xr[d];
    }
    size_t base = (size_t)(t0 + h) * DIMV;
    #pragma unroll
    for (int j = 0; j < 24; ++j) g_y[base + lid + 32 * j] = yv[j];
    float s = 0.f;
    #pragma unroll
    for (int j = 0; j < 24; ++j) s += yv[j];
    float mean = warp_sum(s) * (1.0f / DIMV);
    float s2 = 0.f;
    #pragma unroll
    for (int j = 0; j < 24; ++j) { float d = yv[j] - mean; s2 += d * d; }
    float var = warp_sum(s2) * (1.0f / (DIMV - 1));
    float inv = g2[0] / (sqrtf(var) + 1e-6f);
    float bb = b2[0];
    #pragma unroll
    for (int j = 0; j < 24; ++j)
        g_act[base + lid + 32 * j] = __float2half((yv[j] - mean) * inv + bb);
}

// ---------------- fp16 single-pass GEMM: 128x128 tile, BK=64, 8 warps (2x4, warp 64x32) -
// 2 CTAs/SM. Row pitch 144B (128B data + 16B pad). Stage: 2 x 128 x 144 = 36864 B; 3 stages.
#define PITCH   144
#define ST_A    18432
#define ST_SIZE 36864
#define N_STAGE 3
#define GEMM_SMEM (N_STAGE * ST_SIZE)

// EPI 0: act @ wqkv^T + qkvb  -> g_qkv          (K=768,  N=2304)
// EPI 1: act @ w1^T + d1_b, gelu -> g_h (fp16)  (K=768,  N=3072)
// EPI 2: h @ w2^T + d2_b + g_y -> outF          (K=3072, N=768)
template <int EPI>
__global__ void __launch_bounds__(256, 2) gemm_k(const float* __restrict__ bias, float* __restrict__ outF) {
    constexpr int Kd = (EPI == 2) ? HID : DIMV;
    constexpr int NCH = Kd / 64;
    const __half* A = (EPI == 2) ? g_h : g_act;
    const __half* B = (EPI == 0) ? g_wqkv : (EPI == 1) ? g_w1 : g_w2;

    const int tid = threadIdx.x;
    const int lane = tid & 31, wid = tid >> 5;
    const int wm = wid >> 2, wn = wid & 3;      // 2 x 4 warp grid; warp tile 64 x 32
    const int bx = blockIdx.x, by = blockIdx.y;
    const uint32_t smb = smem_u32(dyn_smem);

    auto load_stage = [&](int c, int st) {
        uint32_t sb = smb + st * ST_SIZE;
        // A: 128 rows x 128B = 1024 cp16 (4/thread)
        #pragma unroll
        for (int j = 0; j < 4; ++j) {
            int id = tid + 256 * j;
            int r = id >> 3, q = id & 7;
            cp16(sb + r * PITCH + q * 16, A + (size_t)(by * 128 + r) * Kd + c * 64 + q * 8);
        }
        // B: 128 rows x 128B = 1024 cp16 (4/thread)
        #pragma unroll
        for (int j = 0; j < 4; ++j) {
            int id = tid + 256 * j;
            int r = id >> 3, q = id & 7;
            cp16(sb + ST_A + r * PITCH + q * 16, B + (size_t)(bx * 128 + r) * Kd + c * 64 + q * 8);
        }
        CP_COMMIT();
    };

    float acc[4][4][4];
    #pragma unroll
    for (int mi = 0; mi < 4; ++mi)
        #pragma unroll
        for (int ni = 0; ni < 4; ++ni)
            #pragma unroll
            for (int r = 0; r < 4; ++r) acc[mi][ni][r] = 0.f;

    load_stage(0, 0);
    load_stage(1, 1);

    for (int c = 0; c < NCH; ++c) {
        CP_WAIT(1);                              // group c complete
        __syncthreads();                         // stage c visible; buf (c+2)%3 free
        if (c + 2 < NCH) load_stage(c + 2, (c + 2) % N_STAGE);

        const uint32_t sb = smb + (c % N_STAGE) * ST_SIZE;
        #pragma unroll
        for (int ks = 0; ks < 4; ++ks) {
            // B frags: ldsm_x4 covers 2 adjacent ni
            uint32_t bf[4][2];
            #pragma unroll
            for (int nb = 0; nb < 2; ++nb) {
                int g = lane >> 3;
                uint32_t bd = sb + ST_A + (uint32_t)(wn * 32 + nb * 16 + (g >> 1) * 8 + (lane & 7)) * PITCH
                            + ks * 32 + (g & 1) * 16;
                uint32_t t[4];
                ldsm_x4(t, bd);
                bf[2 * nb][0] = t[0]; bf[2 * nb][1] = t[1];
                bf[2 * nb + 1][0] = t[2]; bf[2 * nb + 1][1] = t[3];
            }
            #pragma unroll
            for (int mi = 0; mi < 4; ++mi) {
                uint32_t a[4];
                uint32_t ad = sb + (uint32_t)(wm * 64 + mi * 16 + (lane & 15)) * PITCH
                            + ks * 32 + (lane >> 4) * 16;
                ldsm_x4(a, ad);
                #pragma unroll
                for (int ni = 0; ni < 4; ++ni)
                    mma16816h(acc[mi][ni], a, bf[ni]);
            }
        }
    }

    // ---------------- epilogue ----------------
    const int r0 = lane >> 2, c0 = 2 * (lane & 3);
    #pragma unroll
    for (int mi = 0; mi < 4; ++mi) {
        #pragma unroll
        for (int hh = 0; hh < 2; ++hh) {
            const int grow = by * 128 + wm * 64 + mi * 16 + r0 + hh * 8;
            #pragma unroll
            for (int ni = 0; ni < 4; ++ni) {
                const int gcol = bx * 128 + wn * 32 + ni * 8 + c0;
                float v0 = acc[mi][ni][2 * hh + 0];
                float v1 = acc[mi][ni][2 * hh + 1];
                if (EPI == 0) {
                    float2 o;
                    o.x = v0 + g_qkvb[gcol];
                    o.y = v1 + g_qkvb[gcol + 1];
                    *(float2*)(g_qkv + (size_t)grow * NQKV + gcol) = o;
                } else if (EPI == 1) {
                    float u0 = v0 + bias[gcol];
                    float u1 = v1 + bias[gcol + 1];
                    float gl0 = 0.5f * u0 * (1.0f + erff(u0 * 0.70710678118654752440f));
                    float gl1 = 0.5f * u1 * (1.0f + erff(u1 * 0.70710678118654752440f));
                    size_t idx = (size_t)grow * HID + gcol;
                    *(__half2*)(g_h + idx) = __half2(__float2half(gl0), __float2half(gl1));
                } else {
                    size_t idx = (size_t)grow * DIMV + gcol;
                    float2 res = *(const float2*)(g_y + idx);
                    float2 o;
                    o.x = v0 + bias[gcol] + res.x;
                    o.y = v1 + bias[gcol + 1] + res.y;
                    *(float2*)(outF + idx) = o;
                }
            }
        }
    }
}

// ---------------- launch ----------------
#define ATTN_SMEM (2 * 8 * DIMV * (int)sizeof(float))

extern "C" void kernel_launch(void* const* d_in, const int* in_sizes, int n_in,
                              void* d_out, int out_size) {
    const float* x    = (const float*)d_in[0];
    const float* wq_w = (const float*)d_in[1];
    const float* wq_b = (const float*)d_in[2];
    const float* wk_w = (const float*)d_in[3];
    const float* wk_b = (const float*)d_in[4];
    const float* wv_w = (const float*)d_in[5];
    const float* wv_b = (const float*)d_in[6];
    const float* d1_w = (const float*)d_in[7];
    const float* d1_b = (const float*)d_in[8];
    const float* d2_w = (const float*)d_in[9];
    const float* d2_b = (const float*)d_in[10];
    const float* g1   = (const float*)d_in[11];
    const float* b1   = (const float*)d_in[12];
    const float* g2   = (const float*)d_in[13];
    const float* b2   = (const float*)d_in[14];
    float* out = (float*)d_out;

    cudaFuncSetAttribute(gemm_k<0>, cudaFuncAttributeMaxDynamicSharedMemorySize, GEMM_SMEM);
    cudaFuncSetAttribute(gemm_k<1>, cudaFuncAttributeMaxDynamicSharedMemorySize, GEMM_SMEM);
    cudaFuncSetAttribute(gemm_k<2>, cudaFuncAttributeMaxDynamicSharedMemorySize, GEMM_SMEM);
    cudaFuncSetAttribute(attn_ln2_kernel, cudaFuncAttributeMaxDynamicSharedMemorySize, ATTN_SMEM);

    // launch order chosen so ncu (-s 5 -c 1) profiles gemm_k<1>, the largest GEMM
    prep_qkv<<<2048, 256>>>(wq_w, wk_w, wv_w, wq_b, wk_b, wv_b);       // 0
    prep_mlp<<<4096, 256>>>(d1_w, d2_w);                               // 1
    ln1_kernel<<<TTOK / 8, 256>>>(x, g1, b1);                          // 2
    gemm_k<0><<<dim3(NQKV / 128, TTOK / 128), 256, GEMM_SMEM>>>(nullptr, nullptr);  // 3
    attn_ln2_kernel<<<TTOK / 8, 256, ATTN_SMEM>>>(x, g2, b2);          // 4
    gemm_k<1><<<dim3(HID / 128, TTOK / 128), 256, GEMM_SMEM>>>(d1_b, nullptr);      // 5 <- profiled
    gemm_k<2><<<dim3(DIMV / 128, TTOK / 128), 256, GEMM_SMEM>>>(d2_b, out);         // 6
}

// round 10
// speedup vs baseline: 2.8118x; 1.0485x over previous
#include <cuda_runtime.h>
#include <cuda_bf16.h>
#include <cuda_fp16.h>
#include <cstdint>

#define DIMV 768
#define TTOK 16384
#define HID  3072
#define NQKV 2304

// ---------------- device scratch (allocation-free rule: __device__ globals) -------------
__device__ __align__(256) __half g_act[(size_t)TTOK * DIMV];
__device__ __align__(256) float  g_qkv[(size_t)TTOK * NQKV];
__device__ __align__(256) float  g_y[(size_t)TTOK * DIMV];
__device__ __align__(256) __half g_h[(size_t)TTOK * HID];
__device__ __align__(256) __half g_wqkv[(size_t)NQKV * DIMV];
__device__ __align__(256) __half g_w1[(size_t)HID * DIMV];
__device__ __align__(256) __half g_w2[(size_t)DIMV * HID];
__device__ __align__(256) float  g_qkvb[NQKV];

extern __shared__ char dyn_smem[];

// ---------------- PTX helpers ----------------
__device__ __forceinline__ uint32_t smem_u32(const void* p) {
    uint32_t a;
    asm("{ .reg .u64 t; cvta.to.shared.u64 t, %1; cvt.u32.u64 %0, t; }" : "=r"(a) : "l"(p));
    return a;
}
__device__ __forceinline__ void cp16(uint32_t smaddr, const void* g) {
    asm volatile("cp.async.cg.shared.global [%0], [%1], 16;" :: "r"(smaddr), "l"(g) : "memory");
}
#define CP_COMMIT() asm volatile("cp.async.commit_group;" ::: "memory")
#define CP_WAIT(n)  asm volatile("cp.async.wait_group %0;" :: "n"(n) : "memory")

__device__ __forceinline__ void ldsm_x4(uint32_t* r, uint32_t addr) {
    asm volatile("ldmatrix.sync.aligned.m8n8.x4.shared.b16 {%0,%1,%2,%3}, [%4];"
                 : "=r"(r[0]), "=r"(r[1]), "=r"(r[2]), "=r"(r[3]) : "r"(addr));
}
__device__ __forceinline__ void mma16816h(float* c, const uint32_t* a, const uint32_t* b) {
    asm volatile("mma.sync.aligned.m16n8k16.row.col.f32.f16.f16.f32 "
                 "{%0,%1,%2,%3}, {%4,%5,%6,%7}, {%8,%9}, {%0,%1,%2,%3};"
                 : "+f"(c[0]), "+f"(c[1]), "+f"(c[2]), "+f"(c[3])
                 : "r"(a[0]), "r"(a[1]), "r"(a[2]), "r"(a[3]), "r"(b[0]), "r"(b[1]));
}

// ---------------- small helpers ----------------
__device__ __forceinline__ float warp_sum(float v) {
    #pragma unroll
    for (int o = 16; o > 0; o >>= 1) v += __shfl_xor_sync(0xffffffffu, v, o);
    return v;
}

// ---------------- prep kernels ----------------
__global__ void prep_qkv(const float* __restrict__ wq, const float* __restrict__ wk,
                         const float* __restrict__ wv, const float* __restrict__ bq,
                         const float* __restrict__ bk, const float* __restrict__ bv) {
    const int n = DIMV * DIMV;
    for (int i = blockIdx.x * blockDim.x + threadIdx.x; i < 3 * n + NQKV; i += gridDim.x * blockDim.x) {
        if (i < 3 * n) {
            int s = i / n, j = i - s * n;
            const float* w = (s == 0) ? wq : (s == 1) ? wk : wv;
            g_wqkv[(size_t)s * n + j] = __float2half(w[j]);
        } else {
            int j = i - 3 * n;
            g_qkvb[j] = (j < 768) ? bq[j] : (j < 1536) ? bk[j - 768] : bv[j - 1536];
        }
    }
}
__global__ void prep_mlp(const float* __restrict__ d1, const float* __restrict__ d2) {
    const int n = HID * DIMV;
    for (int i = blockIdx.x * blockDim.x + threadIdx.x; i < 2 * n; i += gridDim.x * blockDim.x) {
        if (i < n) g_w1[i] = __float2half(d1[i]);
        else       g_w2[i - n] = __float2half(d2[i - n]);
    }
}

// ---------------- LN1: x -> fp16(layernorm(x)) ; warp per token ----------------
__global__ void ln1_kernel(const float* __restrict__ x, const float* __restrict__ g1,
                           const float* __restrict__ b1) {
    int wid = threadIdx.x >> 5, lid = threadIdx.x & 31;
    int tok = blockIdx.x * 8 + wid;
    const float* xr = x + (size_t)tok * DIMV;
    float xv[24];
    #pragma unroll
    for (int j = 0; j < 24; ++j) xv[j] = xr[lid + 32 * j];
    float s = 0.f;
    #pragma unroll
    for (int j = 0; j < 24; ++j) s += xv[j];
    float mean = warp_sum(s) * (1.0f / DIMV);
    float s2 = 0.f;
    #pragma unroll
    for (int j = 0; j < 24; ++j) { float d = xv[j] - mean; s2 += d * d; }
    float var = warp_sum(s2) * (1.0f / (DIMV - 1));
    float inv = g1[0] / (sqrtf(var) + 1e-6f);
    float bb = b1[0];
    size_t base = (size_t)tok * DIMV;
    #pragma unroll
    for (int j = 0; j < 24; ++j)
        g_act[base + lid + 32 * j] = __float2half((xv[j] - mean) * inv + bb);
}

// ---------------- attention + residual + LN2 ----------------
__global__ void attn_ln2_kernel(const float* __restrict__ x, const float* __restrict__ g2,
                                const float* __restrict__ b2) {
    float* ks = (float*)dyn_smem;
    float* vs = ks + 8 * DIMV;
    int tid = threadIdx.x;
    int wid = tid >> 5, lid = tid & 31;
    int t0 = blockIdx.x * 8;
    for (int i = tid; i < 8 * DIMV; i += 256) {
        int r = i / DIMV, c = i - r * DIMV;
        const float* row = g_qkv + (size_t)(t0 + r) * NQKV;
        ks[i] = row[768 + c];
        vs[i] = row[1536 + c];
    }
    __syncthreads();
    int h = wid;
    const float* qr = g_qkv + (size_t)(t0 + h) * NQKV;
    float qv[24];
    #pragma unroll
    for (int j = 0; j < 24; ++j) qv[j] = qr[lid + 32 * j];
    float p[8];
    #pragma unroll
    for (int kk = 0; kk < 8; ++kk) {
        float acc = 0.f;
        const float* kr = ks + kk * DIMV;
        #pragma unroll
        for (int j = 0; j < 24; ++j) acc += qv[j] * kr[lid + 32 * j];
        p[kk] = acc;
    }
    #pragma unroll
    for (int kk = 0; kk < 8; ++kk) p[kk] = warp_sum(p[kk]) * 0.03608439182435161f;
    float m = p[0];
    #pragma unroll
    for (int kk = 1; kk < 8; ++kk) m = fmaxf(m, p[kk]);
    float se = 0.f;
    #pragma unroll
    for (int kk = 0; kk < 8; ++kk) { p[kk] = __expf(p[kk] - m); se += p[kk]; }
    float rinv = 1.0f / se;
    #pragma unroll
    for (int kk = 0; kk < 8; ++kk) p[kk] *= rinv;
    const float* xr = x + (size_t)(t0 + h) * DIMV;
    float yv[24];
    #pragma unroll
    for (int j = 0; j < 24; ++j) {
        int d = lid + 32 * j;
        float a = 0.f;
        #pragma unroll
        for (int kk = 0; kk < 8; ++kk) a += p[kk] * vs[kk * DIMV + d];
        yv[j] = a + xr[d];
    }
    size_t base = (size_t)(t0 + h) * DIMV;
    #pragma unroll
    for (int j = 0; j < 24; ++j) g_y[base + lid + 32 * j] = yv[j];
    float s = 0.f;
    #pragma unroll
    for (int j = 0; j < 24; ++j) s += yv[j];
    float mean = warp_sum(s) * (1.0f / DIMV);
    float s2 = 0.f;
    #pragma unroll
    for (int j = 0; j < 24; ++j) { float d = yv[j] - mean; s2 += d * d; }
    float var = warp_sum(s2) * (1.0f / (DIMV - 1));
    float inv = g2[0] / (sqrtf(var) + 1e-6f);
    float bb = b2[0];
    #pragma unroll
    for (int j = 0; j < 24; ++j)
        g_act[base + lid + 32 * j] = __float2half((yv[j] - mean) * inv + bb);
}

// ---------------- fp16 GEMM: 128x128 tile, BK=64, 16 warps (4x4, warp 32x32), 2 CTAs/SM -
// Row pitch 144B. Stage: 2 x 128 x 144 = 36864 B; 3 stages = 110592 B.
#define PITCH   144
#define ST_A    18432
#define ST_SIZE 36864
#define N_STAGE 3
#define GEMM_SMEM (N_STAGE * ST_SIZE)

// EPI 0: act @ wqkv^T + qkvb  -> g_qkv          (K=768,  N=2304)
// EPI 1: act @ w1^T + d1_b, gelu -> g_h (fp16)  (K=768,  N=3072)
// EPI 2: h @ w2^T + d2_b + g_y -> outF          (K=3072, N=768)
template <int EPI>
__global__ void __launch_bounds__(512, 2) gemm_k(const float* __restrict__ bias, float* __restrict__ outF) {
    constexpr int Kd = (EPI == 2) ? HID : DIMV;
    constexpr int NCH = Kd / 64;
    const __half* A = (EPI == 2) ? g_h : g_act;
    const __half* B = (EPI == 0) ? g_wqkv : (EPI == 1) ? g_w1 : g_w2;

    const int tid = threadIdx.x;
    const int lane = tid & 31, wid = tid >> 5;
    const int wm = wid >> 2, wn = wid & 3;      // 4 x 4 warp grid; warp tile 32 x 32
    const int bx = blockIdx.x, by = blockIdx.y;
    const uint32_t smb = smem_u32(dyn_smem);

    // precomputed per-thread fragment base offsets (within a stage)
    const uint32_t a_off = (uint32_t)(wm * 32 + (lane & 15)) * PITCH + (lane >> 4) * 16;
    const int g = lane >> 3;
    const uint32_t b_off = ST_A + (uint32_t)(wn * 32 + (g >> 1) * 8 + (lane & 7)) * PITCH + (g & 1) * 16;

    auto load_stage = [&](int c, int st) {
        uint32_t sb = smb + st * ST_SIZE;
        // A: 128 rows x 128B = 1024 cp16 (2/thread)
        #pragma unroll
        for (int j = 0; j < 2; ++j) {
            int id = tid + 512 * j;
            int r = id >> 3, q = id & 7;
            cp16(sb + r * PITCH + q * 16, A + (size_t)(by * 128 + r) * Kd + c * 64 + q * 8);
        }
        // B: 128 rows x 128B = 1024 cp16 (2/thread)
        #pragma unroll
        for (int j = 0; j < 2; ++j) {
            int id = tid + 512 * j;
            int r = id >> 3, q = id & 7;
            cp16(sb + ST_A + r * PITCH + q * 16, B + (size_t)(bx * 128 + r) * Kd + c * 64 + q * 8);
        }
        CP_COMMIT();
    };

    float acc[2][4][4];
    #pragma unroll
    for (int mi = 0; mi < 2; ++mi)
        #pragma unroll
        for (int ni = 0; ni < 4; ++ni)
            #pragma unroll
            for (int r = 0; r < 4; ++r) acc[mi][ni][r] = 0.f;

    load_stage(0, 0);
    load_stage(1, 1);

    for (int c = 0; c < NCH; ++c) {
        CP_WAIT(1);                              // group c complete
        __syncthreads();                         // stage c visible; buf (c+2)%3 free
        if (c + 2 < NCH) load_stage(c + 2, (c + 2) % N_STAGE);

        const uint32_t sb = smb + (c % N_STAGE) * ST_SIZE;
        #pragma unroll
        for (int ks = 0; ks < 4; ++ks) {
            // B frags: 2 ldsm_x4, each covers 2 adjacent ni
            uint32_t bf[4][2];
            #pragma unroll
            for (int nb = 0; nb < 2; ++nb) {
                uint32_t t[4];
                ldsm_x4(t, sb + b_off + nb * (16 * PITCH) + ks * 32);
                bf[2 * nb][0] = t[0]; bf[2 * nb][1] = t[1];
                bf[2 * nb + 1][0] = t[2]; bf[2 * nb + 1][1] = t[3];
            }
            #pragma unroll
            for (int mi = 0; mi < 2; ++mi) {
                uint32_t a[4];
                ldsm_x4(a, sb + a_off + mi * (16 * PITCH) + ks * 32);
                #pragma unroll
                for (int ni = 0; ni < 4; ++ni)
                    mma16816h(acc[mi][ni], a, bf[ni]);
            }
        }
    }

    // ---------------- epilogue ----------------
    const int r0 = lane >> 2, c0 = 2 * (lane & 3);
    #pragma unroll
    for (int mi = 0; mi < 2; ++mi) {
        #pragma unroll
        for (int hh = 0; hh < 2; ++hh) {
            const int grow = by * 128 + wm * 32 + mi * 16 + r0 + hh * 8;
            #pragma unroll
            for (int ni = 0; ni < 4; ++ni) {
                const int gcol = bx * 128 + wn * 32 + ni * 8 + c0;
                float v0 = acc[mi][ni][2 * hh + 0];
                float v1 = acc[mi][ni][2 * hh + 1];
                if (EPI == 0) {
                    float2 o;
                    o.x = v0 + g_qkvb[gcol];
                    o.y = v1 + g_qkvb[gcol + 1];
                    *(float2*)(g_qkv + (size_t)grow * NQKV + gcol) = o;
                } else if (EPI == 1) {
                    float u0 = v0 + bias[gcol];
                    float u1 = v1 + bias[gcol + 1];
                    float gl0 = 0.5f * u0 * (1.0f + erff(u0 * 0.70710678118654752440f));
                    float gl1 = 0.5f * u1 * (1.0f + erff(u1 * 0.70710678118654752440f));
                    size_t idx = (size_t)grow * HID + gcol;
                    *(__half2*)(g_h + idx) = __half2(__float2half(gl0), __float2half(gl1));
                } else {
                    size_t idx = (size_t)grow * DIMV + gcol;
                    float2 res = *(const float2*)(g_y + idx);
                    float2 o;
                    o.x = v0 + bias[gcol] + res.x;
                    o.y = v1 + bias[gcol + 1] + res.y;
                    *(float2*)(outF + idx) = o;
                }
            }
        }
    }
}

// ---------------- launch ----------------
#define ATTN_SMEM (2 * 8 * DIMV * (int)sizeof(float))

extern "C" void kernel_launch(void* const* d_in, const int* in_sizes, int n_in,
                              void* d_out, int out_size) {
    const float* x    = (const float*)d_in[0];
    const float* wq_w = (const float*)d_in[1];
    const float* wq_b = (const float*)d_in[2];
    const float* wk_w = (const float*)d_in[3];
    const float* wk_b = (const float*)d_in[4];
    const float* wv_w = (const float*)d_in[5];
    const float* wv_b = (const float*)d_in[6];
    const float* d1_w = (const float*)d_in[7];
    const float* d1_b = (const float*)d_in[8];
    const float* d2_w = (const float*)d_in[9];
    const float* d2_b = (const float*)d_in[10];
    const float* g1   = (const float*)d_in[11];
    const float* b1   = (const float*)d_in[12];
    const float* g2   = (const float*)d_in[13];
    const float* b2   = (const float*)d_in[14];
    float* out = (float*)d_out;

    cudaFuncSetAttribute(gemm_k<0>, cudaFuncAttributeMaxDynamicSharedMemorySize, GEMM_SMEM);
    cudaFuncSetAttribute(gemm_k<1>, cudaFuncAttributeMaxDynamicSharedMemorySize, GEMM_SMEM);
    cudaFuncSetAttribute(gemm_k<2>, cudaFuncAttributeMaxDynamicSharedMemorySize, GEMM_SMEM);
    cudaFuncSetAttribute(attn_ln2_kernel, cudaFuncAttributeMaxDynamicSharedMemorySize, ATTN_SMEM);

    // launch order chosen so ncu (-s 5 -c 1) profiles gemm_k<1>, the largest GEMM
    prep_qkv<<<2048, 256>>>(wq_w, wk_w, wv_w, wq_b, wk_b, wv_b);       // 0
    prep_mlp<<<4096, 256>>>(d1_w, d2_w);                               // 1
    ln1_kernel<<<TTOK / 8, 256>>>(x, g1, b1);                          // 2
    gemm_k<0><<<dim3(NQKV / 128, TTOK / 128), 512, GEMM_SMEM>>>(nullptr, nullptr);  // 3
    attn_ln2_kernel<<<TTOK / 8, 256, ATTN_SMEM>>>(x, g2, b2);          // 4
    gemm_k<1><<<dim3(HID / 128, TTOK / 128), 512, GEMM_SMEM>>>(d1_b, nullptr);      // 5 <- profiled
    gemm_k<2><<<dim3(DIMV / 128, TTOK / 128), 512, GEMM_SMEM>>>(d2_b, out);         // 6
}